// round 9
// baseline (speedup 1.0000x reference)
#include <cuda_runtime.h>
#include <cuda_fp16.h>
#include <cstdint>
#include <math.h>

// ---------------- problem constants ----------------
#define D      2560
#define SSELF  2048
#define SCROSS 512
#define NB     2
#define NH     20
#define HDIM   128
#define FFND   10240
#define TOK    4096
#define TOKC   1024
#define BH     40
#define EPSV   1e-6f

typedef __half f16;

// ---------------- scratch (device globals) ----------------
__device__ float g_h1  [(size_t)TOK * D];
__device__ float g_h2  [(size_t)TOK * D];

__device__ f16 g_qkvh[(size_t)TOK * 3 * D];
__device__ f16 g_kv2h[(size_t)TOKC * 2 * D];
__device__ f16 g_x[(size_t)TOK * D];
__device__ f16 g_q[(size_t)TOK * D];
__device__ f16 g_a[(size_t)TOK * D];
__device__ f16 g_m[(size_t)TOK * FFND];
__device__ f16 g_P[(size_t)BH * SSELF * SSELF];
__device__ f16 g_enc[(size_t)TOKC * D];
__device__ f16 g_kb[(size_t)TOK * D];
__device__ f16 g_vb[(size_t)TOK * D];
__device__ f16 g_wqkv[(size_t)3 * D * D];
__device__ f16 g_wo1 [(size_t)D * D];
__device__ f16 g_wq2 [(size_t)D * D];
__device__ f16 g_wkv2[(size_t)2 * D * D];
__device__ f16 g_wo2 [(size_t)D * D];
__device__ f16 g_wff1[(size_t)FFND * D];
__device__ f16 g_wff2[(size_t)D * FFND];

// ---------------- small helpers ----------------
__device__ __forceinline__ float fast_gelu(float x) {
    float u = 0.7978845608028654f * (x + 0.044715f * x * x * x);
    float t = 1.0f - 2.0f / (1.0f + __expf(2.0f * u));
    return 0.5f * x * (1.0f + t);
}

__device__ __forceinline__ uint32_t h2_bits(__half2 h) {
    uint32_t u;
    memcpy(&u, &h, 4);
    return u;
}

__device__ __forceinline__ uint32_t smem_u32(const void* p) {
    uint32_t a;
    asm("{ .reg .u64 t; cvta.to.shared.u64 t, %1; cvt.u32.u64 %0, t; }" : "=r"(a) : "l"(p));
    return a;
}

#define CP_ASYNC16(dst, src) \
    asm volatile("cp.async.cg.shared.global [%0], [%1], 16;" :: "r"(dst), "l"(src))
#define CP_COMMIT() asm volatile("cp.async.commit_group;" ::: "memory")
#define CP_WAIT1()  asm volatile("cp.async.wait_group 1;" ::: "memory")

__device__ __forceinline__ void ldsm4(uint32_t* r, uint32_t addr) {
    asm volatile("ldmatrix.sync.aligned.m8n8.x4.shared.b16 {%0,%1,%2,%3}, [%4];"
        : "=r"(r[0]), "=r"(r[1]), "=r"(r[2]), "=r"(r[3]) : "r"(addr));
}

__device__ __forceinline__ void mma16816h(float* c, const uint32_t* a, const uint32_t* b) {
    asm volatile("mma.sync.aligned.m16n8k16.row.col.f32.f16.f16.f32 "
        "{%0,%1,%2,%3}, {%4,%5,%6,%7}, {%8,%9}, {%0,%1,%2,%3};"
        : "+f"(c[0]), "+f"(c[1]), "+f"(c[2]), "+f"(c[3])
        : "r"(a[0]), "r"(a[1]), "r"(a[2]), "r"(a[3]), "r"(b[0]), "r"(b[1]));
}

// ---------------- reductions ----------------
__device__ __forceinline__ float blockReduceSum(float v) {
    __shared__ float sh[32];
    int lane = threadIdx.x & 31, wid = threadIdx.x >> 5;
    #pragma unroll
    for (int o = 16; o > 0; o >>= 1) v += __shfl_xor_sync(0xffffffffu, v, o);
    __syncthreads();
    if (lane == 0) sh[wid] = v;
    __syncthreads();
    int nw = blockDim.x >> 5;
    float r = (threadIdx.x < nw) ? sh[threadIdx.x] : 0.0f;
    if (wid == 0) {
        #pragma unroll
        for (int o = 16; o > 0; o >>= 1) r += __shfl_xor_sync(0xffffffffu, r, o);
        if (lane == 0) sh[0] = r;
    }
    __syncthreads();
    return sh[0];
}

__device__ __forceinline__ float blockReduceMax(float v) {
    __shared__ float sh[32];
    int lane = threadIdx.x & 31, wid = threadIdx.x >> 5;
    #pragma unroll
    for (int o = 16; o > 0; o >>= 1) v = fmaxf(v, __shfl_xor_sync(0xffffffffu, v, o));
    __syncthreads();
    if (lane == 0) sh[wid] = v;
    __syncthreads();
    int nw = blockDim.x >> 5;
    float r = (threadIdx.x < nw) ? sh[threadIdx.x] : -3.4e38f;
    if (wid == 0) {
        #pragma unroll
        for (int o = 16; o > 0; o >>= 1) r = fmaxf(r, __shfl_xor_sync(0xffffffffu, r, o));
        if (lane == 0) sh[0] = r;
    }
    __syncthreads();
    return sh[0];
}

// ---------------- elementwise producers ----------------
__global__ void __launch_bounds__(256) ln_kernel(
    const float* __restrict__ in, f16* __restrict__ ob,
    const float* __restrict__ gamma, const float* __restrict__ beta,
    const float* __restrict__ sst, const float* __restrict__ temb,
    int iShift, int iScale, int rowsPerB)
{
    long long r = blockIdx.x;
    const float* x = in + r * D;
    float s1 = 0.f, s2 = 0.f;
    for (int d = threadIdx.x; d < D; d += 256) { float v = x[d]; s1 += v; s2 += v * v; }
    s1 = blockReduceSum(s1);
    s2 = blockReduceSum(s2);
    float mean = s1 * (1.0f / D);
    float var  = s2 * (1.0f / D) - mean * mean;
    float rstd = rsqrtf(var + EPSV);
    int b = (int)(r / rowsPerB);
    for (int d = threadIdx.x; d < D; d += 256) {
        float y = (x[d] - mean) * rstd;
        if (sst) {
            float sc = sst[iScale * D + d] + temb[((long long)b * 6 + iScale) * D + d];
            float sh = sst[iShift * D + d] + temb[((long long)b * 6 + iShift) * D + d];
            y = y * (1.f + sc) + sh;
        } else if (gamma) {
            y = y * gamma[d] + beta[d];
        }
        ob[r * D + d] = __float2half_rn(y);
    }
}

// RMS + optional rope over fp16 input rows
__global__ void __launch_bounds__(256) rms_heads_kernel(
    const f16* __restrict__ in, int ldin, int off,
    const float* __restrict__ w, f16* __restrict__ ob, int Srows,
    const float* __restrict__ rcos, const float* __restrict__ rsin)
{
    long long r = blockIdx.x;
    int b = (int)(r / Srows), s = (int)(r % Srows);
    const f16* x = in + r * ldin + off;
    float s2 = 0.f;
    for (int d = threadIdx.x; d < D; d += 256) { float v = __half2float(x[d]); s2 += v * v; }
    s2 = blockReduceSum(s2);
    float rms = rsqrtf(s2 * (1.0f / D) + EPSV);
    for (int d = threadIdx.x; d < D; d += 256) {
        int h = d >> 7, dd = d & 127;
        float v = __half2float(x[d]) * rms * w[d];
        if (rcos) {
            int pd = (dd < 64) ? d + 64 : d - 64;
            float vp = __half2float(x[pd]) * rms * w[pd];
            float c = rcos[s * HDIM + dd], sn = rsin[s * HDIM + dd];
            v = (dd < 64) ? (v * c - vp * sn) : (v * c + vp * sn);
        }
        ob[(((long long)(b * NH + h)) * Srows + s) * HDIM + dd] = __float2half_rn(v);
    }
}

// V tiled transpose: in [B*Srows, ldin] f16 (v slice at off) -> out [B*NH*HDIM, Srows]
__global__ void vtrans_kernel(
    const f16* __restrict__ in, int ldin, int off,
    f16* __restrict__ out, int Srows)
{
    __shared__ f16 tile[32][33];
    int bz = blockIdx.z;                 // b*NH + h
    int b = bz / NH, h = bz % NH;
    int s0 = blockIdx.x * 32, d0 = blockIdx.y * 32;
    int tx = threadIdx.x, ty = threadIdx.y;
    int colBase = off + h * HDIM + d0;
    #pragma unroll
    for (int i = 0; i < 4; i++) {
        int s = s0 + ty + i * 8;
        tile[ty + i * 8][tx] = in[(long long)(b * Srows + s) * ldin + colBase + tx];
    }
    __syncthreads();
    #pragma unroll
    for (int i = 0; i < 4; i++) {
        int d = d0 + ty + i * 8;
        out[((long long)bz * HDIM + d) * Srows + s0 + tx] = tile[tx][ty + i * 8];
    }
}

// softmax in place on fp16 rows (fp32 math in registers)
__global__ void __launch_bounds__(256) softmax_kernel(f16* __restrict__ p, int len)
{
    long long r = blockIdx.x;
    f16* x = p + r * (long long)len;
    int nper = len >> 8;           // 8 for 2048, 2 for 512
    float xv[8];
    float mx = -3.4e38f;
    for (int i = 0; i < nper; i++) {
        xv[i] = __half2float(x[threadIdx.x + (i << 8)]);
        mx = fmaxf(mx, xv[i]);
    }
    mx = blockReduceMax(mx);
    float sum = 0.f;
    for (int i = 0; i < nper; i++) { xv[i] = __expf(xv[i] - mx); sum += xv[i]; }
    sum = blockReduceSum(sum);
    float inv = 1.0f / sum;
    for (int i = 0; i < nper; i++)
        x[threadIdx.x + (i << 8)] = __float2half_rn(xv[i] * inv);
}

// fp32 -> fp16, vectorized 8 elems/thread-iter (n must be divisible by 8)
__global__ void __launch_bounds__(256) conv_kernel(
    const float* __restrict__ in, f16* __restrict__ ob, long long n)
{
    long long n8 = n >> 3;
    const float4* in4 = (const float4*)in;
    uint4* o4 = (uint4*)ob;
    for (long long i = blockIdx.x * 256LL + threadIdx.x; i < n8; i += (long long)gridDim.x * 256) {
        float4 a = in4[2 * i], b = in4[2 * i + 1];
        uint4 o;
        o.x = h2_bits(__floats2half2_rn(a.x, a.y));
        o.y = h2_bits(__floats2half2_rn(a.z, a.w));
        o.z = h2_bits(__floats2half2_rn(b.x, b.y));
        o.w = h2_bits(__floats2half2_rn(b.z, b.w));
        o4[i] = o;
    }
}

// ---------------- fp16 single-product GEMM ----------------
#define STAGE_BYTES 16384
#define OFF_A 0
#define OFF_B 8192
#define NSTAGE 3
#define GEMM_SMEM (NSTAGE * STAGE_BYTES)

__device__ __forceinline__ uint32_t tswz(int row, int chunk) {
    return (uint32_t)(row * 64 + ((chunk ^ (row & 3)) << 4));
}

__global__ void __launch_bounds__(256, 2) gemm_h1_kernel(
    const f16* __restrict__ A, const f16* __restrict__ B,
    float* __restrict__ C, f16* __restrict__ Cf,
    int K, int lda, int ldb, int ldc,
    long long sAo, long long sAi, long long sBo, long long sBi,
    long long sCo, long long sCi, int innerN,
    const float* __restrict__ bias, float alpha, int mode,
    const float* __restrict__ res,
    const float* __restrict__ sst, const float* __restrict__ temb,
    int modIdx)
{
    extern __shared__ char smem[];
    uint32_t sbase = smem_u32(smem);
    int tid = threadIdx.x, wid = tid >> 5, lane = tid & 31;

    int bi = blockIdx.z;
    long long aBase = (long long)(bi / innerN) * sAo + (long long)(bi % innerN) * sAi;
    long long bBase = (long long)(bi / innerN) * sBo + (long long)(bi % innerN) * sBi;
    long long cBase = (long long)(bi / innerN) * sCo + (long long)(bi % innerN) * sCi;
    int m0 = blockIdx.y * 128, n0 = blockIdx.x * 128;

    const f16* Ap = A + aBase + (long long)m0 * lda;
    const f16* Bp = B + bBase + (long long)n0 * ldb;

    int lrow = tid >> 2, lch = tid & 3;
    int NC = K >> 5;

    auto load_stage = [&](int c) {
        int s = c % NSTAGE;
        uint32_t st = sbase + s * STAGE_BYTES;
        int k0 = c << 5;
        #pragma unroll
        for (int half = 0; half < 2; half++) {
            int row = lrow + half * 64;
            uint32_t sw = tswz(row, lch);
            long long gk = k0 + lch * 8;
            CP_ASYNC16(st + OFF_A + sw, Ap + (long long)row * lda + gk);
            CP_ASYNC16(st + OFF_B + sw, Bp + (long long)row * ldb + gk);
        }
    };

    float acc[4][4][4];
    #pragma unroll
    for (int i = 0; i < 4; i++)
        #pragma unroll
        for (int j = 0; j < 4; j++)
            #pragma unroll
            for (int e = 0; e < 4; e++) acc[i][j][e] = 0.f;

    int wm = (wid >> 2) * 64, wn = (wid & 3) * 32;

    load_stage(0); CP_COMMIT();
    if (NC > 1) load_stage(1);
    CP_COMMIT();

    for (int c = 0; c < NC; c++) {
        int s = c % NSTAGE;
        CP_WAIT1();
        __syncthreads();
        if (c + 2 < NC) load_stage(c + 2);
        CP_COMMIT();

        uint32_t st = sbase + s * STAGE_BYTES;
        #pragma unroll
        for (int kk = 0; kk < 2; kk++) {
            uint32_t ah[4][4], bh[4][2];
            int rA = lane & 15, cA = (kk << 1) + (lane >> 4);
            #pragma unroll
            for (int mt = 0; mt < 4; mt++)
                ldsm4(ah[mt], st + OFF_A + tswz(wm + mt * 16 + rA, cA));
            int rB = (lane & 7) + ((lane >> 4) << 3);
            int cB = (kk << 1) + ((lane >> 3) & 1);
            #pragma unroll
            for (int ntp = 0; ntp < 2; ntp++) {
                uint32_t t[4];
                ldsm4(t, st + OFF_B + tswz(wn + ntp * 16 + rB, cB));
                bh[2*ntp][0]=t[0]; bh[2*ntp][1]=t[1]; bh[2*ntp+1][0]=t[2]; bh[2*ntp+1][1]=t[3];
            }
            #pragma unroll
            for (int mt = 0; mt < 4; mt++)
                #pragma unroll
                for (int nt = 0; nt < 4; nt++)
                    mma16816h(acc[mt][nt], ah[mt], bh[nt]);
        }
    }

    // ---- epilogue ----
    int qrow = lane >> 2, qcol = (lane & 3) * 2;
    #pragma unroll
    for (int mt = 0; mt < 4; mt++) {
        #pragma unroll
        for (int nt = 0; nt < 4; nt++) {
            #pragma unroll
            for (int e = 0; e < 4; e++) {
                long long rrow = m0 + wm + mt * 16 + qrow + ((e >> 1) ? 8 : 0);
                int col = n0 + wn + nt * 8 + qcol + (e & 1);
                float v = acc[mt][nt][e] * alpha;
                if (bias) v += bias[col];
                if (mode == 1) v = fast_gelu(v);
                long long ci = cBase + rrow * ldc + col;
                if (mode == 2) {
                    int b_ = (int)(rrow >> 11);  // 2048 rows per batch
                    float g = sst[(long long)modIdx * D + col] +
                              temb[((long long)b_ * 6 + modIdx) * D + col];
                    v = res[ci] + g * v;
                } else if (mode == 3) {
                    v = res[ci] + v;
                }
                if (C)  C[ci]  = v;
                if (Cf) Cf[ci] = __float2half_rn(v);
            }
        }
    }
}

// ---------------- host launch helper ----------------
static void gemm(const f16* A, const f16* B, float* C, f16* Cf,
                 int M, int N, int K, int lda, int ldb, int ldc,
                 long long sAo, long long sAi, long long sBo, long long sBi,
                 long long sCo, long long sCi, int innerN, int nbatch,
                 const float* bias, float alpha, int mode,
                 const float* res, const float* sst, const float* temb,
                 int modIdx)
{
    dim3 grid(N / 128, M / 128, nbatch), block(256);
    gemm_h1_kernel<<<grid, block, GEMM_SMEM>>>(
        A, B, C, Cf, K, lda, ldb, ldc,
        sAo, sAi, sBo, sBi, sCo, sCi, innerN,
        bias, alpha, mode, res, sst, temb, modIdx);
}

#define GETP(sym) ({ void* _p; cudaGetSymbolAddress(&_p, sym); _p; })

extern "C" void kernel_launch(void* const* d_in, const int* in_sizes, int n_in,
                              void* d_out, int out_size)
{
    const float* h    = (const float*)d_in[0];
    const float* enc  = (const float*)d_in[1];
    const float* temb = (const float*)d_in[2];
    const float* rcos = (const float*)d_in[3];
    const float* rsin = (const float*)d_in[4];
    const float* sst  = (const float*)d_in[5];
    const float* w_qkv = (const float*)d_in[6];
    const float* b_qkv = (const float*)d_in[7];
    const float* rms_q1 = (const float*)d_in[8];
    const float* rms_k1 = (const float*)d_in[9];
    const float* w_o1 = (const float*)d_in[10];
    const float* b_o1 = (const float*)d_in[11];
    const float* ln2_g = (const float*)d_in[12];
    const float* ln2_b = (const float*)d_in[13];
    const float* w_q2 = (const float*)d_in[14];
    const float* b_q2 = (const float*)d_in[15];
    const float* w_kv2 = (const float*)d_in[16];
    const float* b_kv2 = (const float*)d_in[17];
    const float* rms_q2 = (const float*)d_in[18];
    const float* rms_k2 = (const float*)d_in[19];
    const float* w_o2 = (const float*)d_in[20];
    const float* b_o2 = (const float*)d_in[21];
    const float* w_ff1 = (const float*)d_in[22];
    const float* b_ff1 = (const float*)d_in[23];
    const float* w_ff2 = (const float*)d_in[24];
    const float* b_ff2 = (const float*)d_in[25];
    float* out = (float*)d_out;

    cudaFuncSetAttribute(gemm_h1_kernel, cudaFuncAttributeMaxDynamicSharedMemorySize, GEMM_SMEM);

    float* ph1  = (float*)GETP(g_h1);
    float* ph2  = (float*)GETP(g_h2);
    f16 *qkvh=(f16*)GETP(g_qkvh);
    f16 *kv2h=(f16*)GETP(g_kv2h);
    f16 *xb=(f16*)GETP(g_x);
    f16 *qb=(f16*)GETP(g_q);
    f16 *ab=(f16*)GETP(g_a);
    f16 *mb=(f16*)GETP(g_m);
    f16 *Pb=(f16*)GETP(g_P);
    f16 *encb=(f16*)GETP(g_enc);
    f16 *kb=(f16*)GETP(g_kb), *vb=(f16*)GETP(g_vb);
    f16 *wqkv=(f16*)GETP(g_wqkv);
    f16 *wo1=(f16*)GETP(g_wo1);
    f16 *wq2=(f16*)GETP(g_wq2);
    f16 *wkv2=(f16*)GETP(g_wkv2);
    f16 *wo2=(f16*)GETP(g_wo2);
    f16 *wff1=(f16*)GETP(g_wff1);
    f16 *wff2=(f16*)GETP(g_wff2);

    const float scale = 0.08838834764831845f;
    const long long uQ  = (long long)SSELF * HDIM;
    const long long uL  = (long long)SSELF * SSELF;
    const long long uV  = (long long)HDIM * SSELF;
    const long long uK2 = (long long)SCROSS * HDIM;
    const long long uL2 = (long long)SSELF * SCROSS;
    const long long uV2 = (long long)HDIM * SCROSS;

    // 0) ln ; 1) conv wqkv ; 2) conv wo1 ; 3) qkv GEMM (profiled = idx 3)
    ln_kernel<<<TOK, 256>>>(h, xb, nullptr, nullptr, sst, temb, 0, 1, SSELF);
    conv_kernel<<<1024, 256>>>(w_qkv, wqkv, (long long)3 * D * D);
    conv_kernel<<<512, 256>>>(w_o1, wo1, (long long)D * D);
    gemm(xb, wqkv, nullptr, qkvh, TOK, 3 * D, D, D, D, 3 * D,
         0,0,0,0,0,0,1,1, b_qkv, 1.f, 0, nullptr, nullptr, nullptr, 0);
    // other converts
    conv_kernel<<<512, 256>>>(w_q2,  wq2,  (long long)D * D);
    conv_kernel<<<512, 256>>>(w_kv2, wkv2, (long long)2 * D * D);
    conv_kernel<<<512, 256>>>(w_o2,  wo2,  (long long)D * D);
    conv_kernel<<<1024, 256>>>(w_ff1, wff1, (long long)FFND * D);
    conv_kernel<<<1024, 256>>>(w_ff2, wff2, (long long)D * FFND);
    conv_kernel<<<512, 256>>>(enc,  encb, (long long)TOKC * D);
    // heads
    rms_heads_kernel<<<TOK, 256>>>(qkvh, 3 * D, 0, rms_q1, qb, SSELF, rcos, rsin);
    rms_heads_kernel<<<TOK, 256>>>(qkvh, 3 * D, D, rms_k1, kb, SSELF, rcos, rsin);
    {
        dim3 tb(32, 8), tg(SSELF / 32, HDIM / 32, BH);
        vtrans_kernel<<<tg, tb>>>(qkvh, 3 * D, 2 * D, vb, SSELF);
    }
    // logits = scale * q k^T -> fp16 (in place softmax after)
    gemm(qb, kb, nullptr, Pb, SSELF, SSELF, HDIM, HDIM, HDIM, SSELF,
         NH * uQ, uQ, NH * uQ, uQ, NH * uL, uL, NH, BH,
         nullptr, scale, 0, nullptr, nullptr, nullptr, 0);
    softmax_kernel<<<BH * SSELF, 256>>>(Pb, SSELF);
    // attn = P @ V -> fp16 merged [TOK, D]
    gemm(Pb, vb, nullptr, ab, SSELF, HDIM, SSELF, SSELF, SSELF, D,
         NH * uL, uL, NH * uV, uV, (long long)SSELF * D, HDIM, NH, BH,
         nullptr, 1.f, 0, nullptr, nullptr, nullptr, 0);
    // h1 = h + gate_sa * (attn W_o1^T + b)
    gemm(ab, wo1, ph1, nullptr, TOK, D, D, D, D, D,
         0,0,0,0,0,0,1,1, b_o1, 1.f, 2, h, sst, temb, 2);
    // x2 = LN(h1)
    ln_kernel<<<TOK, 256>>>(ph1, xb, ln2_g, ln2_b, nullptr, nullptr, 0, 0, SSELF);
    // q2lin -> fp16
    gemm(xb, wq2, nullptr, qkvh, TOK, D, D, D, D, D,
         0,0,0,0,0,0,1,1, b_q2, 1.f, 0, nullptr, nullptr, nullptr, 0);
    rms_heads_kernel<<<TOK, 256>>>(qkvh, D, 0, rms_q2, qb, SSELF, nullptr, nullptr);
    // kv2 = enc @ w_kv2^T + b -> fp16
    gemm(encb, wkv2, nullptr, kv2h, TOKC, 2 * D, D, D, D, 2 * D,
         0,0,0,0,0,0,1,1, b_kv2, 1.f, 0, nullptr, nullptr, nullptr, 0);
    rms_heads_kernel<<<TOKC, 256>>>(kv2h, 2 * D, 0, rms_k2, kb, SCROSS, nullptr, nullptr);
    {
        dim3 tb(32, 8), tg(SCROSS / 32, HDIM / 32, BH);
        vtrans_kernel<<<tg, tb>>>(kv2h, 2 * D, D, vb, SCROSS);
    }
    // logits2 -> fp16
    gemm(qb, kb, nullptr, Pb, SSELF, SCROSS, HDIM, HDIM, HDIM, SCROSS,
         NH * uQ, uQ, NH * uK2, uK2, NH * uL2, uL2, NH, BH,
         nullptr, scale, 0, nullptr, nullptr, nullptr, 0);
    softmax_kernel<<<BH * SSELF, 256>>>(Pb, SCROSS);
    // attn2
    gemm(Pb, vb, nullptr, ab, SSELF, HDIM, SCROSS, SCROSS, SCROSS, D,
         NH * uL2, uL2, NH * uV2, uV2, (long long)SSELF * D, HDIM, NH, BH,
         nullptr, 1.f, 0, nullptr, nullptr, nullptr, 0);
    // h2 = h1 + attn2 W_o2^T + b
    gemm(ab, wo2, ph2, nullptr, TOK, D, D, D, D, D,
         0,0,0,0,0,0,1,1, b_o2, 1.f, 3, ph1, nullptr, nullptr, 0);
    // xff
    ln_kernel<<<TOK, 256>>>(ph2, xb, nullptr, nullptr, sst, temb, 3, 4, SSELF);
    // mid = gelu(xff W_ff1^T + b) -> fp16
    gemm(xb, wff1, nullptr, mb, TOK, FFND, D, D, D, FFND,
         0,0,0,0,0,0,1,1, b_ff1, 1.f, 1, nullptr, nullptr, nullptr, 0);
    // out = h2 + gate_ff * (mid W_ff2^T + b)
    gemm(mb, wff2, out, nullptr, TOK, D, FFND, FFND, FFND, D,
         0,0,0,0,0,0,1,1, b_ff2, 1.f, 2, ph2, sst, temb, 5);

    (void)in_sizes; (void)n_in; (void)out_size;
}

// round 10
// speedup vs baseline: 1.0511x; 1.0511x over previous
#include <cuda_runtime.h>
#include <cuda_fp16.h>
#include <cstdint>
#include <math.h>

// ---------------- problem constants ----------------
#define D      2560
#define SSELF  2048
#define SCROSS 512
#define NB     2
#define NH     20
#define HDIM   128
#define FFND   10240
#define TOK    4096
#define TOKC   1024
#define BH     40
#define EPSV   1e-6f

typedef __half f16;

// ---------------- scratch (device globals) ----------------
__device__ float g_h1  [(size_t)TOK * D];
__device__ float g_h2  [(size_t)TOK * D];

__device__ f16 g_qkvh[(size_t)TOK * 3 * D];
__device__ f16 g_kv2h[(size_t)TOKC * 2 * D];
__device__ f16 g_x[(size_t)TOK * D];
__device__ f16 g_q[(size_t)TOK * D];
__device__ f16 g_a[(size_t)TOK * D];
__device__ f16 g_m[(size_t)TOK * FFND];
__device__ f16 g_P[(size_t)BH * SSELF * SSELF];
__device__ f16 g_enc[(size_t)TOKC * D];
__device__ f16 g_kb[(size_t)TOK * D];
__device__ f16 g_vb[(size_t)TOK * D];
__device__ f16 g_wqkv[(size_t)3 * D * D];
__device__ f16 g_wo1 [(size_t)D * D];
__device__ f16 g_wq2 [(size_t)D * D];
__device__ f16 g_wkv2[(size_t)2 * D * D];
__device__ f16 g_wo2 [(size_t)D * D];
__device__ f16 g_wff1[(size_t)FFND * D];
__device__ f16 g_wff2[(size_t)D * FFND];

// ---------------- small helpers ----------------
__device__ __forceinline__ float fast_gelu(float x) {
    float u = 0.7978845608028654f * (x + 0.044715f * x * x * x);
    float t = 1.0f - 2.0f / (1.0f + __expf(2.0f * u));
    return 0.5f * x * (1.0f + t);
}

__device__ __forceinline__ uint32_t h2_bits(__half2 h) {
    uint32_t u;
    memcpy(&u, &h, 4);
    return u;
}

__device__ __forceinline__ uint32_t smem_u32(const void* p) {
    uint32_t a;
    asm("{ .reg .u64 t; cvta.to.shared.u64 t, %1; cvt.u32.u64 %0, t; }" : "=r"(a) : "l"(p));
    return a;
}

#define CP_ASYNC16(dst, src) \
    asm volatile("cp.async.cg.shared.global [%0], [%1], 16;" :: "r"(dst), "l"(src))
#define CP_COMMIT() asm volatile("cp.async.commit_group;" ::: "memory")
#define CP_WAIT1()  asm volatile("cp.async.wait_group 1;" ::: "memory")

__device__ __forceinline__ void ldsm4(uint32_t* r, uint32_t addr) {
    asm volatile("ldmatrix.sync.aligned.m8n8.x4.shared.b16 {%0,%1,%2,%3}, [%4];"
        : "=r"(r[0]), "=r"(r[1]), "=r"(r[2]), "=r"(r[3]) : "r"(addr));
}

__device__ __forceinline__ void mma16816h(float* c, const uint32_t* a, const uint32_t* b) {
    asm volatile("mma.sync.aligned.m16n8k16.row.col.f32.f16.f16.f32 "
        "{%0,%1,%2,%3}, {%4,%5,%6,%7}, {%8,%9}, {%0,%1,%2,%3};"
        : "+f"(c[0]), "+f"(c[1]), "+f"(c[2]), "+f"(c[3])
        : "r"(a[0]), "r"(a[1]), "r"(a[2]), "r"(a[3]), "r"(b[0]), "r"(b[1]));
}

// ---------------- reductions ----------------
__device__ __forceinline__ float blockReduceSum(float v) {
    __shared__ float sh[32];
    int lane = threadIdx.x & 31, wid = threadIdx.x >> 5;
    #pragma unroll
    for (int o = 16; o > 0; o >>= 1) v += __shfl_xor_sync(0xffffffffu, v, o);
    __syncthreads();
    if (lane == 0) sh[wid] = v;
    __syncthreads();
    int nw = blockDim.x >> 5;
    float r = (threadIdx.x < nw) ? sh[threadIdx.x] : 0.0f;
    if (wid == 0) {
        #pragma unroll
        for (int o = 16; o > 0; o >>= 1) r += __shfl_xor_sync(0xffffffffu, r, o);
        if (lane == 0) sh[0] = r;
    }
    __syncthreads();
    return sh[0];
}

__device__ __forceinline__ float blockReduceMax(float v) {
    __shared__ float sh[32];
    int lane = threadIdx.x & 31, wid = threadIdx.x >> 5;
    #pragma unroll
    for (int o = 16; o > 0; o >>= 1) v = fmaxf(v, __shfl_xor_sync(0xffffffffu, v, o));
    __syncthreads();
    if (lane == 0) sh[wid] = v;
    __syncthreads();
    int nw = blockDim.x >> 5;
    float r = (threadIdx.x < nw) ? sh[threadIdx.x] : -3.4e38f;
    if (wid == 0) {
        #pragma unroll
        for (int o = 16; o > 0; o >>= 1) r = fmaxf(r, __shfl_xor_sync(0xffffffffu, r, o));
        if (lane == 0) sh[0] = r;
    }
    __syncthreads();
    return sh[0];
}

// ---------------- elementwise producers ----------------
__global__ void __launch_bounds__(256) ln_kernel(
    const float* __restrict__ in, f16* __restrict__ ob,
    const float* __restrict__ gamma, const float* __restrict__ beta,
    const float* __restrict__ sst, const float* __restrict__ temb,
    int iShift, int iScale, int rowsPerB)
{
    long long r = blockIdx.x;
    const float* x = in + r * D;
    float s1 = 0.f, s2 = 0.f;
    for (int d = threadIdx.x; d < D; d += 256) { float v = x[d]; s1 += v; s2 += v * v; }
    s1 = blockReduceSum(s1);
    s2 = blockReduceSum(s2);
    float mean = s1 * (1.0f / D);
    float var  = s2 * (1.0f / D) - mean * mean;
    float rstd = rsqrtf(var + EPSV);
    int b = (int)(r / rowsPerB);
    for (int d = threadIdx.x; d < D; d += 256) {
        float y = (x[d] - mean) * rstd;
        if (sst) {
            float sc = sst[iScale * D + d] + temb[((long long)b * 6 + iScale) * D + d];
            float sh = sst[iShift * D + d] + temb[((long long)b * 6 + iShift) * D + d];
            y = y * (1.f + sc) + sh;
        } else if (gamma) {
            y = y * gamma[d] + beta[d];
        }
        ob[r * D + d] = __float2half_rn(y);
    }
}

__global__ void __launch_bounds__(256) rms_heads_kernel(
    const f16* __restrict__ in, int ldin, int off,
    const float* __restrict__ w, f16* __restrict__ ob, int Srows,
    const float* __restrict__ rcos, const float* __restrict__ rsin)
{
    long long r = blockIdx.x;
    int b = (int)(r / Srows), s = (int)(r % Srows);
    const f16* x = in + r * ldin + off;
    float s2 = 0.f;
    for (int d = threadIdx.x; d < D; d += 256) { float v = __half2float(x[d]); s2 += v * v; }
    s2 = blockReduceSum(s2);
    float rms = rsqrtf(s2 * (1.0f / D) + EPSV);
    for (int d = threadIdx.x; d < D; d += 256) {
        int h = d >> 7, dd = d & 127;
        float v = __half2float(x[d]) * rms * w[d];
        if (rcos) {
            int pd = (dd < 64) ? d + 64 : d - 64;
            float vp = __half2float(x[pd]) * rms * w[pd];
            float c = rcos[s * HDIM + dd], sn = rsin[s * HDIM + dd];
            v = (dd < 64) ? (v * c - vp * sn) : (v * c + vp * sn);
        }
        ob[(((long long)(b * NH + h)) * Srows + s) * HDIM + dd] = __float2half_rn(v);
    }
}

__global__ void vtrans_kernel(
    const f16* __restrict__ in, int ldin, int off,
    f16* __restrict__ out, int Srows)
{
    __shared__ f16 tile[32][33];
    int bz = blockIdx.z;                 // b*NH + h
    int b = bz / NH, h = bz % NH;
    int s0 = blockIdx.x * 32, d0 = blockIdx.y * 32;
    int tx = threadIdx.x, ty = threadIdx.y;
    int colBase = off + h * HDIM + d0;
    #pragma unroll
    for (int i = 0; i < 4; i++) {
        int s = s0 + ty + i * 8;
        tile[ty + i * 8][tx] = in[(long long)(b * Srows + s) * ldin + colBase + tx];
    }
    __syncthreads();
    #pragma unroll
    for (int i = 0; i < 4; i++) {
        int d = d0 + ty + i * 8;
        out[((long long)bz * HDIM + d) * Srows + s0 + tx] = tile[tx][ty + i * 8];
    }
}

__global__ void __launch_bounds__(256) softmax_kernel(f16* __restrict__ p, int len)
{
    long long r = blockIdx.x;
    f16* x = p + r * (long long)len;
    int nper = len >> 8;
    float xv[8];
    float mx = -3.4e38f;
    for (int i = 0; i < nper; i++) {
        xv[i] = __half2float(x[threadIdx.x + (i << 8)]);
        mx = fmaxf(mx, xv[i]);
    }
    mx = blockReduceMax(mx);
    float sum = 0.f;
    for (int i = 0; i < nper; i++) { xv[i] = __expf(xv[i] - mx); sum += xv[i]; }
    sum = blockReduceSum(sum);
    float inv = 1.0f / sum;
    for (int i = 0; i < nper; i++)
        x[threadIdx.x + (i << 8)] = __float2half_rn(xv[i] * inv);
}

__global__ void __launch_bounds__(256) conv_kernel(
    const float* __restrict__ in, f16* __restrict__ ob, long long n)
{
    long long n8 = n >> 3;
    const float4* in4 = (const float4*)in;
    uint4* o4 = (uint4*)ob;
    for (long long i = blockIdx.x * 256LL + threadIdx.x; i < n8; i += (long long)gridDim.x * 256) {
        float4 a = in4[2 * i], b = in4[2 * i + 1];
        uint4 o;
        o.x = h2_bits(__floats2half2_rn(a.x, a.y));
        o.y = h2_bits(__floats2half2_rn(a.z, a.w));
        o.z = h2_bits(__floats2half2_rn(b.x, b.y));
        o.w = h2_bits(__floats2half2_rn(b.z, b.w));
        o4[i] = o;
    }
}

// ---------------- fp16 single-product GEMM, 64x64 warp tiles ----------------
// BM=BN=128, BK=32, 4 warps (2x2 grid of 64x64 tiles), 3-stage cp.async, 2 CTAs/SM
#define STAGE_BYTES 16384
#define OFF_A 0
#define OFF_B 8192
#define NSTAGE 3
#define GEMM_SMEM (NSTAGE * STAGE_BYTES)

__device__ __forceinline__ uint32_t tswz(int row, int chunk) {
    return (uint32_t)(row * 64 + ((chunk ^ (row & 3)) << 4));
}

__global__ void __launch_bounds__(128, 2) gemm_h1_kernel(
    const f16* __restrict__ A, const f16* __restrict__ B,
    float* __restrict__ C, f16* __restrict__ Cf,
    int K, int lda, int ldb, int ldc,
    long long sAo, long long sAi, long long sBo, long long sBi,
    long long sCo, long long sCi, int innerN,
    const float* __restrict__ bias, float alpha, int mode,
    const float* __restrict__ res,
    const float* __restrict__ sst, const float* __restrict__ temb,
    int modIdx)
{
    extern __shared__ char smem[];
    uint32_t sbase = smem_u32(smem);
    int tid = threadIdx.x, wid = tid >> 5, lane = tid & 31;

    int bi = blockIdx.z;
    long long aBase = (long long)(bi / innerN) * sAo + (long long)(bi % innerN) * sAi;
    long long bBase = (long long)(bi / innerN) * sBo + (long long)(bi % innerN) * sBi;
    long long cBase = (long long)(bi / innerN) * sCo + (long long)(bi % innerN) * sCi;
    int m0 = blockIdx.y * 128, n0 = blockIdx.x * 128;

    const f16* Ap = A + aBase + (long long)m0 * lda;
    const f16* Bp = B + bBase + (long long)n0 * ldb;

    // loader: 128 threads, 8 chunks each (4 A rows + 4 B rows)
    int lrow = tid >> 2, lch = tid & 3;   // lrow 0..31, lch 0..3
    int NC = K >> 5;

    auto load_stage = [&](int c) {
        int s = c % NSTAGE;
        uint32_t st = sbase + s * STAGE_BYTES;
        int k0 = c << 5;
        #pragma unroll
        for (int q = 0; q < 4; q++) {
            int row = lrow + q * 32;
            uint32_t sw = tswz(row, lch);
            long long gk = k0 + lch * 8;
            CP_ASYNC16(st + OFF_A + sw, Ap + (long long)row * lda + gk);
            CP_ASYNC16(st + OFF_B + sw, Bp + (long long)row * ldb + gk);
        }
    };

    float acc[4][8][4];
    #pragma unroll
    for (int i = 0; i < 4; i++)
        #pragma unroll
        for (int j = 0; j < 8; j++)
            #pragma unroll
            for (int e = 0; e < 4; e++) acc[i][j][e] = 0.f;

    int wm = (wid >> 1) * 64, wn = (wid & 1) * 64;

    load_stage(0); CP_COMMIT();
    if (NC > 1) load_stage(1);
    CP_COMMIT();

    for (int c = 0; c < NC; c++) {
        int s = c % NSTAGE;
        CP_WAIT1();
        __syncthreads();
        if (c + 2 < NC) load_stage(c + 2);
        CP_COMMIT();

        uint32_t st = sbase + s * STAGE_BYTES;
        #pragma unroll
        for (int kk = 0; kk < 2; kk++) {
            uint32_t ah[4][4], bfr[8][2];
            int rA = lane & 15, cA = (kk << 1) + (lane >> 4);
            #pragma unroll
            for (int mt = 0; mt < 4; mt++)
                ldsm4(ah[mt], st + OFF_A + tswz(wm + mt * 16 + rA, cA));
            int rB = (lane & 7) + ((lane >> 4) << 3);
            int cB = (kk << 1) + ((lane >> 3) & 1);
            #pragma unroll
            for (int ntp = 0; ntp < 4; ntp++) {
                uint32_t t[4];
                ldsm4(t, st + OFF_B + tswz(wn + ntp * 16 + rB, cB));
                bfr[2*ntp][0]=t[0]; bfr[2*ntp][1]=t[1]; bfr[2*ntp+1][0]=t[2]; bfr[2*ntp+1][1]=t[3];
            }
            #pragma unroll
            for (int mt = 0; mt < 4; mt++)
                #pragma unroll
                for (int nt = 0; nt < 8; nt++)
                    mma16816h(acc[mt][nt], ah[mt], bfr[nt]);
        }
    }

    // ---- epilogue ----
    int qrow = lane >> 2, qcol = (lane & 3) * 2;
    #pragma unroll
    for (int mt = 0; mt < 4; mt++) {
        #pragma unroll
        for (int nt = 0; nt < 8; nt++) {
            #pragma unroll
            for (int e = 0; e < 4; e++) {
                long long rrow = m0 + wm + mt * 16 + qrow + ((e >> 1) ? 8 : 0);
                int col = n0 + wn + nt * 8 + qcol + (e & 1);
                float v = acc[mt][nt][e] * alpha;
                if (bias) v += bias[col];
                if (mode == 1) v = fast_gelu(v);
                long long ci = cBase + rrow * ldc + col;
                if (mode == 2) {
                    int b_ = (int)(rrow >> 11);
                    float g = sst[(long long)modIdx * D + col] +
                              temb[((long long)b_ * 6 + modIdx) * D + col];
                    v = res[ci] + g * v;
                } else if (mode == 3) {
                    v = res[ci] + v;
                }
                if (C)  C[ci]  = v;
                if (Cf) Cf[ci] = __float2half_rn(v);
            }
        }
    }
}

// ---------------- host launch helper ----------------
static void gemm(const f16* A, const f16* B, float* C, f16* Cf,
                 int M, int N, int K, int lda, int ldb, int ldc,
                 long long sAo, long long sAi, long long sBo, long long sBi,
                 long long sCo, long long sCi, int innerN, int nbatch,
                 const float* bias, float alpha, int mode,
                 const float* res, const float* sst, const float* temb,
                 int modIdx)
{
    dim3 grid(N / 128, M / 128, nbatch), block(128);
    gemm_h1_kernel<<<grid, block, GEMM_SMEM>>>(
        A, B, C, Cf, K, lda, ldb, ldc,
        sAo, sAi, sBo, sBi, sCo, sCi, innerN,
        bias, alpha, mode, res, sst, temb, modIdx);
}

#define GETP(sym) ({ void* _p; cudaGetSymbolAddress(&_p, sym); _p; })

extern "C" void kernel_launch(void* const* d_in, const int* in_sizes, int n_in,
                              void* d_out, int out_size)
{
    const float* h    = (const float*)d_in[0];
    const float* enc  = (const float*)d_in[1];
    const float* temb = (const float*)d_in[2];
    const float* rcos = (const float*)d_in[3];
    const float* rsin = (const float*)d_in[4];
    const float* sst  = (const float*)d_in[5];
    const float* w_qkv = (const float*)d_in[6];
    const float* b_qkv = (const float*)d_in[7];
    const float* rms_q1 = (const float*)d_in[8];
    const float* rms_k1 = (const float*)d_in[9];
    const float* w_o1 = (const float*)d_in[10];
    const float* b_o1 = (const float*)d_in[11];
    const float* ln2_g = (const float*)d_in[12];
    const float* ln2_b = (const float*)d_in[13];
    const float* w_q2 = (const float*)d_in[14];
    const float* b_q2 = (const float*)d_in[15];
    const float* w_kv2 = (const float*)d_in[16];
    const float* b_kv2 = (const float*)d_in[17];
    const float* rms_q2 = (const float*)d_in[18];
    const float* rms_k2 = (const float*)d_in[19];
    const float* w_o2 = (const float*)d_in[20];
    const float* b_o2 = (const float*)d_in[21];
    const float* w_ff1 = (const float*)d_in[22];
    const float* b_ff1 = (const float*)d_in[23];
    const float* w_ff2 = (const float*)d_in[24];
    const float* b_ff2 = (const float*)d_in[25];
    float* out = (float*)d_out;

    cudaFuncSetAttribute(gemm_h1_kernel, cudaFuncAttributeMaxDynamicSharedMemorySize, GEMM_SMEM);

    float* ph1  = (float*)GETP(g_h1);
    float* ph2  = (float*)GETP(g_h2);
    f16 *qkvh=(f16*)GETP(g_qkvh);
    f16 *kv2h=(f16*)GETP(g_kv2h);
    f16 *xb=(f16*)GETP(g_x);
    f16 *qb=(f16*)GETP(g_q);
    f16 *ab=(f16*)GETP(g_a);
    f16 *mb=(f16*)GETP(g_m);
    f16 *Pb=(f16*)GETP(g_P);
    f16 *encb=(f16*)GETP(g_enc);
    f16 *kb=(f16*)GETP(g_kb), *vb=(f16*)GETP(g_vb);
    f16 *wqkv=(f16*)GETP(g_wqkv);
    f16 *wo1=(f16*)GETP(g_wo1);
    f16 *wq2=(f16*)GETP(g_wq2);
    f16 *wkv2=(f16*)GETP(g_wkv2);
    f16 *wo2=(f16*)GETP(g_wo2);
    f16 *wff1=(f16*)GETP(g_wff1);
    f16 *wff2=(f16*)GETP(g_wff2);

    const float scale = 0.08838834764831845f;
    const long long uQ  = (long long)SSELF * HDIM;
    const long long uL  = (long long)SSELF * SSELF;
    const long long uV  = (long long)HDIM * SSELF;
    const long long uK2 = (long long)SCROSS * HDIM;
    const long long uL2 = (long long)SSELF * SCROSS;
    const long long uV2 = (long long)HDIM * SCROSS;

    // 0) ln ; 1) conv wqkv ; 2) conv wo1 ; 3) qkv GEMM (profiled = idx 3)
    ln_kernel<<<TOK, 256>>>(h, xb, nullptr, nullptr, sst, temb, 0, 1, SSELF);
    conv_kernel<<<1024, 256>>>(w_qkv, wqkv, (long long)3 * D * D);
    conv_kernel<<<512, 256>>>(w_o1, wo1, (long long)D * D);
    gemm(xb, wqkv, nullptr, qkvh, TOK, 3 * D, D, D, D, 3 * D,
         0,0,0,0,0,0,1,1, b_qkv, 1.f, 0, nullptr, nullptr, nullptr, 0);
    // other converts
    conv_kernel<<<512, 256>>>(w_q2,  wq2,  (long long)D * D);
    conv_kernel<<<512, 256>>>(w_kv2, wkv2, (long long)2 * D * D);
    conv_kernel<<<512, 256>>>(w_o2,  wo2,  (long long)D * D);
    conv_kernel<<<1024, 256>>>(w_ff1, wff1, (long long)FFND * D);
    conv_kernel<<<1024, 256>>>(w_ff2, wff2, (long long)D * FFND);
    conv_kernel<<<512, 256>>>(enc,  encb, (long long)TOKC * D);
    // heads
    rms_heads_kernel<<<TOK, 256>>>(qkvh, 3 * D, 0, rms_q1, qb, SSELF, rcos, rsin);
    rms_heads_kernel<<<TOK, 256>>>(qkvh, 3 * D, D, rms_k1, kb, SSELF, rcos, rsin);
    {
        dim3 tb(32, 8), tg(SSELF / 32, HDIM / 32, BH);
        vtrans_kernel<<<tg, tb>>>(qkvh, 3 * D, 2 * D, vb, SSELF);
    }
    // logits = scale * q k^T -> fp16 (softmax in place)
    gemm(qb, kb, nullptr, Pb, SSELF, SSELF, HDIM, HDIM, HDIM, SSELF,
         NH * uQ, uQ, NH * uQ, uQ, NH * uL, uL, NH, BH,
         nullptr, scale, 0, nullptr, nullptr, nullptr, 0);
    softmax_kernel<<<BH * SSELF, 256>>>(Pb, SSELF);
    // attn = P @ V -> fp16 merged [TOK, D]
    gemm(Pb, vb, nullptr, ab, SSELF, HDIM, SSELF, SSELF, SSELF, D,
         NH * uL, uL, NH * uV, uV, (long long)SSELF * D, HDIM, NH, BH,
         nullptr, 1.f, 0, nullptr, nullptr, nullptr, 0);
    // h1 = h + gate_sa * (attn W_o1^T + b)
    gemm(ab, wo1, ph1, nullptr, TOK, D, D, D, D, D,
         0,0,0,0,0,0,1,1, b_o1, 1.f, 2, h, sst, temb, 2);
    // x2 = LN(h1)
    ln_kernel<<<TOK, 256>>>(ph1, xb, ln2_g, ln2_b, nullptr, nullptr, 0, 0, SSELF);
    // q2lin -> fp16
    gemm(xb, wq2, nullptr, qkvh, TOK, D, D, D, D, D,
         0,0,0,0,0,0,1,1, b_q2, 1.f, 0, nullptr, nullptr, nullptr, 0);
    rms_heads_kernel<<<TOK, 256>>>(qkvh, D, 0, rms_q2, qb, SSELF, nullptr, nullptr);
    // kv2 = enc @ w_kv2^T + b -> fp16
    gemm(encb, wkv2, nullptr, kv2h, TOKC, 2 * D, D, D, D, 2 * D,
         0,0,0,0,0,0,1,1, b_kv2, 1.f, 0, nullptr, nullptr, nullptr, 0);
    rms_heads_kernel<<<TOKC, 256>>>(kv2h, 2 * D, 0, rms_k2, kb, SCROSS, nullptr, nullptr);
    {
        dim3 tb(32, 8), tg(SCROSS / 32, HDIM / 32, BH);
        vtrans_kernel<<<tg, tb>>>(kv2h, 2 * D, D, vb, SCROSS);
    }
    // logits2 -> fp16
    gemm(qb, kb, nullptr, Pb, SSELF, SCROSS, HDIM, HDIM, HDIM, SCROSS,
         NH * uQ, uQ, NH * uK2, uK2, NH * uL2, uL2, NH, BH,
         nullptr, scale, 0, nullptr, nullptr, nullptr, 0);
    softmax_kernel<<<BH * SSELF, 256>>>(Pb, SCROSS);
    // attn2
    gemm(Pb, vb, nullptr, ab, SSELF, HDIM, SCROSS, SCROSS, SCROSS, D,
         NH * uL2, uL2, NH * uV2, uV2, (long long)SSELF * D, HDIM, NH, BH,
         nullptr, 1.f, 0, nullptr, nullptr, nullptr, 0);
    // h2 = h1 + attn2 W_o2^T + b
    gemm(ab, wo2, ph2, nullptr, TOK, D, D, D, D, D,
         0,0,0,0,0,0,1,1, b_o2, 1.f, 3, ph1, nullptr, nullptr, 0);
    // xff
    ln_kernel<<<TOK, 256>>>(ph2, xb, nullptr, nullptr, sst, temb, 3, 4, SSELF);
    // mid = gelu(xff W_ff1^T + b) -> fp16
    gemm(xb, wff1, nullptr, mb, TOK, FFND, D, D, D, FFND,
         0,0,0,0,0,0,1,1, b_ff1, 1.f, 1, nullptr, nullptr, nullptr, 0);
    // out = h2 + gate_ff * (mid W_ff2^T + b)
    gemm(mb, wff2, out, nullptr, TOK, D, FFND, FFND, FFND, D,
         0,0,0,0,0,0,1,1, b_ff2, 1.f, 2, ph2, sst, temb, 5);

    (void)in_sizes; (void)n_in; (void)out_size;
}

// round 11
// speedup vs baseline: 1.2821x; 1.2197x over previous
#include <cuda_runtime.h>
#include <cuda_fp16.h>
#include <cstdint>
#include <math.h>

// ---------------- problem constants ----------------
#define D      2560
#define SSELF  2048
#define SCROSS 512
#define NB     2
#define NH     20
#define HDIM   128
#define FFND   10240
#define TOK    4096
#define TOKC   1024
#define BH     40
#define EPSV   1e-6f

typedef __half f16;

// ---------------- scratch (device globals) ----------------
__device__ float g_h1  [(size_t)TOK * D];
__device__ float g_h2  [(size_t)TOK * D];

__device__ f16 g_qkvh[(size_t)TOK * 3 * D];
__device__ f16 g_kv2h[(size_t)TOKC * 2 * D];
__device__ f16 g_x[(size_t)TOK * D];
__device__ f16 g_q[(size_t)TOK * D];
__device__ f16 g_a[(size_t)TOK * D];
__device__ f16 g_m[(size_t)TOK * FFND];
__device__ f16 g_P[(size_t)BH * SSELF * SSELF];
__device__ f16 g_enc[(size_t)TOKC * D];
__device__ f16 g_kb[(size_t)TOK * D];
__device__ f16 g_vb[(size_t)TOK * D];
__device__ f16 g_wqkv[(size_t)3 * D * D];
__device__ f16 g_wo1 [(size_t)D * D];
__device__ f16 g_wq2 [(size_t)D * D];
__device__ f16 g_wkv2[(size_t)2 * D * D];
__device__ f16 g_wo2 [(size_t)D * D];
__device__ f16 g_wff1[(size_t)FFND * D];
__device__ f16 g_wff2[(size_t)D * FFND];

// ---------------- small helpers ----------------
__device__ __forceinline__ float fast_gelu(float x) {
    float u = 0.7978845608028654f * (x + 0.044715f * x * x * x);
    float t = 1.0f - 2.0f / (1.0f + __expf(2.0f * u));
    return 0.5f * x * (1.0f + t);
}

__device__ __forceinline__ uint32_t h2_bits(__half2 h) {
    uint32_t u;
    memcpy(&u, &h, 4);
    return u;
}

__device__ __forceinline__ uint32_t smem_u32(const void* p) {
    uint32_t a;
    asm("{ .reg .u64 t; cvta.to.shared.u64 t, %1; cvt.u32.u64 %0, t; }" : "=r"(a) : "l"(p));
    return a;
}

#define CP_ASYNC16(dst, src) \
    asm volatile("cp.async.cg.shared.global [%0], [%1], 16;" :: "r"(dst), "l"(src))
#define CP_COMMIT() asm volatile("cp.async.commit_group;" ::: "memory")
#define CP_WAIT1()  asm volatile("cp.async.wait_group 1;" ::: "memory")

__device__ __forceinline__ void ldsm4(uint32_t* r, uint32_t addr) {
    asm volatile("ldmatrix.sync.aligned.m8n8.x4.shared.b16 {%0,%1,%2,%3}, [%4];"
        : "=r"(r[0]), "=r"(r[1]), "=r"(r[2]), "=r"(r[3]) : "r"(addr));
}

__device__ __forceinline__ void mma16816h(float* c, const uint32_t* a, const uint32_t* b) {
    asm volatile("mma.sync.aligned.m16n8k16.row.col.f32.f16.f16.f32 "
        "{%0,%1,%2,%3}, {%4,%5,%6,%7}, {%8,%9}, {%0,%1,%2,%3};"
        : "+f"(c[0]), "+f"(c[1]), "+f"(c[2]), "+f"(c[3])
        : "r"(a[0]), "r"(a[1]), "r"(a[2]), "r"(a[3]), "r"(b[0]), "r"(b[1]));
}

// ---------------- reductions ----------------
__device__ __forceinline__ float blockReduceSum(float v) {
    __shared__ float sh[32];
    int lane = threadIdx.x & 31, wid = threadIdx.x >> 5;
    #pragma unroll
    for (int o = 16; o > 0; o >>= 1) v += __shfl_xor_sync(0xffffffffu, v, o);
    __syncthreads();
    if (lane == 0) sh[wid] = v;
    __syncthreads();
    int nw = blockDim.x >> 5;
    float r = (threadIdx.x < nw) ? sh[threadIdx.x] : 0.0f;
    if (wid == 0) {
        #pragma unroll
        for (int o = 16; o > 0; o >>= 1) r += __shfl_xor_sync(0xffffffffu, r, o);
        if (lane == 0) sh[0] = r;
    }
    __syncthreads();
    return sh[0];
}

__device__ __forceinline__ float blockReduceMax(float v) {
    __shared__ float sh[32];
    int lane = threadIdx.x & 31, wid = threadIdx.x >> 5;
    #pragma unroll
    for (int o = 16; o > 0; o >>= 1) v = fmaxf(v, __shfl_xor_sync(0xffffffffu, v, o));
    __syncthreads();
    if (lane == 0) sh[wid] = v;
    __syncthreads();
    int nw = blockDim.x >> 5;
    float r = (threadIdx.x < nw) ? sh[threadIdx.x] : -3.4e38f;
    if (wid == 0) {
        #pragma unroll
        for (int o = 16; o > 0; o >>= 1) r = fmaxf(r, __shfl_xor_sync(0xffffffffu, r, o));
        if (lane == 0) sh[0] = r;
    }
    __syncthreads();
    return sh[0];
}

// ---------------- elementwise producers ----------------
__global__ void __launch_bounds__(256) ln_kernel(
    const float* __restrict__ in, f16* __restrict__ ob,
    const float* __restrict__ gamma, const float* __restrict__ beta,
    const float* __restrict__ sst, const float* __restrict__ temb,
    int iShift, int iScale, int rowsPerB)
{
    long long r = blockIdx.x;
    const float* x = in + r * D;
    float s1 = 0.f, s2 = 0.f;
    for (int d = threadIdx.x; d < D; d += 256) { float v = x[d]; s1 += v; s2 += v * v; }
    s1 = blockReduceSum(s1);
    s2 = blockReduceSum(s2);
    float mean = s1 * (1.0f / D);
    float var  = s2 * (1.0f / D) - mean * mean;
    float rstd = rsqrtf(var + EPSV);
    int b = (int)(r / rowsPerB);
    for (int d = threadIdx.x; d < D; d += 256) {
        float y = (x[d] - mean) * rstd;
        if (sst) {
            float sc = sst[iScale * D + d] + temb[((long long)b * 6 + iScale) * D + d];
            float sh = sst[iShift * D + d] + temb[((long long)b * 6 + iShift) * D + d];
            y = y * (1.f + sc) + sh;
        } else if (gamma) {
            y = y * gamma[d] + beta[d];
        }
        ob[r * D + d] = __float2half_rn(y);
    }
}

__global__ void __launch_bounds__(256) rms_heads_kernel(
    const f16* __restrict__ in, int ldin, int off,
    const float* __restrict__ w, f16* __restrict__ ob, int Srows,
    const float* __restrict__ rcos, const float* __restrict__ rsin)
{
    long long r = blockIdx.x;
    int b = (int)(r / Srows), s = (int)(r % Srows);
    const f16* x = in + r * ldin + off;
    float s2 = 0.f;
    for (int d = threadIdx.x; d < D; d += 256) { float v = __half2float(x[d]); s2 += v * v; }
    s2 = blockReduceSum(s2);
    float rms = rsqrtf(s2 * (1.0f / D) + EPSV);
    for (int d = threadIdx.x; d < D; d += 256) {
        int h = d >> 7, dd = d & 127;
        float v = __half2float(x[d]) * rms * w[d];
        if (rcos) {
            int pd = (dd < 64) ? d + 64 : d - 64;
            float vp = __half2float(x[pd]) * rms * w[pd];
            float c = rcos[s * HDIM + dd], sn = rsin[s * HDIM + dd];
            v = (dd < 64) ? (v * c - vp * sn) : (v * c + vp * sn);
        }
        ob[(((long long)(b * NH + h)) * Srows + s) * HDIM + dd] = __float2half_rn(v);
    }
}

__global__ void vtrans_kernel(
    const f16* __restrict__ in, int ldin, int off,
    f16* __restrict__ out, int Srows)
{
    __shared__ f16 tile[32][33];
    int bz = blockIdx.z;
    int b = bz / NH, h = bz % NH;
    int s0 = blockIdx.x * 32, d0 = blockIdx.y * 32;
    int tx = threadIdx.x, ty = threadIdx.y;
    int colBase = off + h * HDIM + d0;
    #pragma unroll
    for (int i = 0; i < 4; i++) {
        int s = s0 + ty + i * 8;
        tile[ty + i * 8][tx] = in[(long long)(b * Srows + s) * ldin + colBase + tx];
    }
    __syncthreads();
    #pragma unroll
    for (int i = 0; i < 4; i++) {
        int d = d0 + ty + i * 8;
        out[((long long)bz * HDIM + d) * Srows + s0 + tx] = tile[tx][ty + i * 8];
    }
}

__global__ void __launch_bounds__(256) softmax_kernel(f16* __restrict__ p, int len)
{
    long long r = blockIdx.x;
    f16* x = p + r * (long long)len;
    int nper = len >> 8;
    float xv[8];
    float mx = -3.4e38f;
    for (int i = 0; i < nper; i++) {
        xv[i] = __half2float(x[threadIdx.x + (i << 8)]);
        mx = fmaxf(mx, xv[i]);
    }
    mx = blockReduceMax(mx);
    float sum = 0.f;
    for (int i = 0; i < nper; i++) { xv[i] = __expf(xv[i] - mx); sum += xv[i]; }
    sum = blockReduceSum(sum);
    float inv = 1.0f / sum;
    for (int i = 0; i < nper; i++)
        x[threadIdx.x + (i << 8)] = __float2half_rn(xv[i] * inv);
}

__global__ void __launch_bounds__(256) conv_kernel(
    const float* __restrict__ in, f16* __restrict__ ob, long long n)
{
    long long n8 = n >> 3;
    const float4* in4 = (const float4*)in;
    uint4* o4 = (uint4*)ob;
    for (long long i = blockIdx.x * 256LL + threadIdx.x; i < n8; i += (long long)gridDim.x * 256) {
        float4 a = in4[2 * i], b = in4[2 * i + 1];
        uint4 o;
        o.x = h2_bits(__floats2half2_rn(a.x, a.y));
        o.y = h2_bits(__floats2half2_rn(a.z, a.w));
        o.z = h2_bits(__floats2half2_rn(b.x, b.y));
        o.w = h2_bits(__floats2half2_rn(b.z, b.w));
        o4[i] = o;
    }
}

// ---------------- fp16 single-product GEMM, 64x64 warp tiles, BK=64 ----------------
// BM=BN=128, BK=64 (128-byte rows), 4 warps (2x2 of 64x64), 3-stage cp.async, 2 CTAs/SM
#define STAGE_BYTES 32768
#define OFF_A 0
#define OFF_B 16384
#define NSTAGE 3
#define GEMM_SMEM (NSTAGE * STAGE_BYTES)

// 128-byte rows, 8 x 16B chunks, XOR-8 swizzle
__device__ __forceinline__ uint32_t tswz(int row, int chunk) {
    return (uint32_t)(row * 128 + ((chunk ^ (row & 7)) << 4));
}

__global__ void __launch_bounds__(128, 2) gemm_h1_kernel(
    const f16* __restrict__ A, const f16* __restrict__ B,
    float* __restrict__ C, f16* __restrict__ Cf,
    int K, int lda, int ldb, int ldc,
    long long sAo, long long sAi, long long sBo, long long sBi,
    long long sCo, long long sCi, int innerN,
    const float* __restrict__ bias, float alpha, int mode,
    const float* __restrict__ res,
    const float* __restrict__ sst, const float* __restrict__ temb,
    int modIdx)
{
    extern __shared__ char smem[];
    uint32_t sbase = smem_u32(smem);
    int tid = threadIdx.x, wid = tid >> 5, lane = tid & 31;

    int bi = blockIdx.z;
    long long aBase = (long long)(bi / innerN) * sAo + (long long)(bi % innerN) * sAi;
    long long bBase = (long long)(bi / innerN) * sBo + (long long)(bi % innerN) * sBi;
    long long cBase = (long long)(bi / innerN) * sCo + (long long)(bi % innerN) * sCi;
    int m0 = blockIdx.y * 128, n0 = blockIdx.x * 128;

    const f16* Ap = A + aBase + (long long)m0 * lda;
    const f16* Bp = B + bBase + (long long)n0 * ldb;

    // loader: 128 threads; per stage: A 128 rows x 128B + B 128 rows x 128B
    int lrow = tid >> 3, lch = tid & 7;   // lrow 0..15, lch 0..7
    int NC = K >> 6;

    auto load_stage = [&](int c) {
        int s = c % NSTAGE;
        uint32_t st = sbase + s * STAGE_BYTES;
        int k0 = c << 6;
        #pragma unroll
        for (int q = 0; q < 8; q++) {
            int row = lrow + q * 16;
            uint32_t sw = tswz(row, lch);
            long long gk = k0 + lch * 8;
            CP_ASYNC16(st + OFF_A + sw, Ap + (long long)row * lda + gk);
            CP_ASYNC16(st + OFF_B + sw, Bp + (long long)row * ldb + gk);
        }
    };

    float acc[4][8][4];
    #pragma unroll
    for (int i = 0; i < 4; i++)
        #pragma unroll
        for (int j = 0; j < 8; j++)
            #pragma unroll
            for (int e = 0; e < 4; e++) acc[i][j][e] = 0.f;

    int wm = (wid >> 1) * 64, wn = (wid & 1) * 64;

    load_stage(0); CP_COMMIT();
    if (NC > 1) load_stage(1);
    CP_COMMIT();

    for (int c = 0; c < NC; c++) {
        int s = c % NSTAGE;
        CP_WAIT1();
        __syncthreads();
        if (c + 2 < NC) load_stage(c + 2);
        CP_COMMIT();

        uint32_t st = sbase + s * STAGE_BYTES;
        #pragma unroll
        for (int kk = 0; kk < 4; kk++) {
            uint32_t ah[4][4], bfr[8][2];
            int rA = lane & 15, cA = (kk << 1) + (lane >> 4);
            #pragma unroll
            for (int mt = 0; mt < 4; mt++)
                ldsm4(ah[mt], st + OFF_A + tswz(wm + mt * 16 + rA, cA));
            int rB = (lane & 7) + ((lane >> 4) << 3);
            int cB = (kk << 1) + ((lane >> 3) & 1);
            #pragma unroll
            for (int ntp = 0; ntp < 4; ntp++) {
                uint32_t t[4];
                ldsm4(t, st + OFF_B + tswz(wn + ntp * 16 + rB, cB));
                bfr[2*ntp][0]=t[0]; bfr[2*ntp][1]=t[1]; bfr[2*ntp+1][0]=t[2]; bfr[2*ntp+1][1]=t[3];
            }
            #pragma unroll
            for (int mt = 0; mt < 4; mt++)
                #pragma unroll
                for (int nt = 0; nt < 8; nt++)
                    mma16816h(acc[mt][nt], ah[mt], bfr[nt]);
        }
    }

    // ---- epilogue ----
    int qrow = lane >> 2, qcol = (lane & 3) * 2;
    #pragma unroll
    for (int mt = 0; mt < 4; mt++) {
        #pragma unroll
        for (int nt = 0; nt < 8; nt++) {
            #pragma unroll
            for (int e = 0; e < 4; e++) {
                long long rrow = m0 + wm + mt * 16 + qrow + ((e >> 1) ? 8 : 0);
                int col = n0 + wn + nt * 8 + qcol + (e & 1);
                float v = acc[mt][nt][e] * alpha;
                if (bias) v += bias[col];
                if (mode == 1) v = fast_gelu(v);
                long long ci = cBase + rrow * ldc + col;
                if (mode == 2) {
                    int b_ = (int)(rrow >> 11);
                    float g = sst[(long long)modIdx * D + col] +
                              temb[((long long)b_ * 6 + modIdx) * D + col];
                    v = res[ci] + g * v;
                } else if (mode == 3) {
                    v = res[ci] + v;
                }
                if (C)  C[ci]  = v;
                if (Cf) Cf[ci] = __float2half_rn(v);
            }
        }
    }
}

// ---------------- host launch helper ----------------
static void gemm(const f16* A, const f16* B, float* C, f16* Cf,
                 int M, int N, int K, int lda, int ldb, int ldc,
                 long long sAo, long long sAi, long long sBo, long long sBi,
                 long long sCo, long long sCi, int innerN, int nbatch,
                 const float* bias, float alpha, int mode,
                 const float* res, const float* sst, const float* temb,
                 int modIdx)
{
    dim3 grid(N / 128, M / 128, nbatch), block(128);
    gemm_h1_kernel<<<grid, block, GEMM_SMEM>>>(
        A, B, C, Cf, K, lda, ldb, ldc,
        sAo, sAi, sBo, sBi, sCo, sCi, innerN,
        bias, alpha, mode, res, sst, temb, modIdx);
}

#define GETP(sym) ({ void* _p; cudaGetSymbolAddress(&_p, sym); _p; })

extern "C" void kernel_launch(void* const* d_in, const int* in_sizes, int n_in,
                              void* d_out, int out_size)
{
    const float* h    = (const float*)d_in[0];
    const float* enc  = (const float*)d_in[1];
    const float* temb = (const float*)d_in[2];
    const float* rcos = (const float*)d_in[3];
    const float* rsin = (const float*)d_in[4];
    const float* sst  = (const float*)d_in[5];
    const float* w_qkv = (const float*)d_in[6];
    const float* b_qkv = (const float*)d_in[7];
    const float* rms_q1 = (const float*)d_in[8];
    const float* rms_k1 = (const float*)d_in[9];
    const float* w_o1 = (const float*)d_in[10];
    const float* b_o1 = (const float*)d_in[11];
    const float* ln2_g = (const float*)d_in[12];
    const float* ln2_b = (const float*)d_in[13];
    const float* w_q2 = (const float*)d_in[14];
    const float* b_q2 = (const float*)d_in[15];
    const float* w_kv2 = (const float*)d_in[16];
    const float* b_kv2 = (const float*)d_in[17];
    const float* rms_q2 = (const float*)d_in[18];
    const float* rms_k2 = (const float*)d_in[19];
    const float* w_o2 = (const float*)d_in[20];
    const float* b_o2 = (const float*)d_in[21];
    const float* w_ff1 = (const float*)d_in[22];
    const float* b_ff1 = (const float*)d_in[23];
    const float* w_ff2 = (const float*)d_in[24];
    const float* b_ff2 = (const float*)d_in[25];
    float* out = (float*)d_out;

    cudaFuncSetAttribute(gemm_h1_kernel, cudaFuncAttributeMaxDynamicSharedMemorySize, GEMM_SMEM);

    float* ph1  = (float*)GETP(g_h1);
    float* ph2  = (float*)GETP(g_h2);
    f16 *qkvh=(f16*)GETP(g_qkvh);
    f16 *kv2h=(f16*)GETP(g_kv2h);
    f16 *xb=(f16*)GETP(g_x);
    f16 *qb=(f16*)GETP(g_q);
    f16 *ab=(f16*)GETP(g_a);
    f16 *mb=(f16*)GETP(g_m);
    f16 *Pb=(f16*)GETP(g_P);
    f16 *encb=(f16*)GETP(g_enc);
    f16 *kb=(f16*)GETP(g_kb), *vb=(f16*)GETP(g_vb);
    f16 *wqkv=(f16*)GETP(g_wqkv);
    f16 *wo1=(f16*)GETP(g_wo1);
    f16 *wq2=(f16*)GETP(g_wq2);
    f16 *wkv2=(f16*)GETP(g_wkv2);
    f16 *wo2=(f16*)GETP(g_wo2);
    f16 *wff1=(f16*)GETP(g_wff1);
    f16 *wff2=(f16*)GETP(g_wff2);

    const float scale = 0.08838834764831845f;
    const long long uQ  = (long long)SSELF * HDIM;
    const long long uL  = (long long)SSELF * SSELF;
    const long long uV  = (long long)HDIM * SSELF;
    const long long uK2 = (long long)SCROSS * HDIM;
    const long long uL2 = (long long)SSELF * SCROSS;
    const long long uV2 = (long long)HDIM * SCROSS;

    // 0) ln ; 1) conv wqkv ; 2) conv wo1 ; 3) qkv GEMM (profiled = idx 3)
    ln_kernel<<<TOK, 256>>>(h, xb, nullptr, nullptr, sst, temb, 0, 1, SSELF);
    conv_kernel<<<1024, 256>>>(w_qkv, wqkv, (long long)3 * D * D);
    conv_kernel<<<512, 256>>>(w_o1, wo1, (long long)D * D);
    gemm(xb, wqkv, nullptr, qkvh, TOK, 3 * D, D, D, D, 3 * D,
         0,0,0,0,0,0,1,1, b_qkv, 1.f, 0, nullptr, nullptr, nullptr, 0);
    // other converts
    conv_kernel<<<512, 256>>>(w_q2,  wq2,  (long long)D * D);
    conv_kernel<<<512, 256>>>(w_kv2, wkv2, (long long)2 * D * D);
    conv_kernel<<<512, 256>>>(w_o2,  wo2,  (long long)D * D);
    conv_kernel<<<1024, 256>>>(w_ff1, wff1, (long long)FFND * D);
    conv_kernel<<<1024, 256>>>(w_ff2, wff2, (long long)D * FFND);
    conv_kernel<<<512, 256>>>(enc,  encb, (long long)TOKC * D);
    // heads
    rms_heads_kernel<<<TOK, 256>>>(qkvh, 3 * D, 0, rms_q1, qb, SSELF, rcos, rsin);
    rms_heads_kernel<<<TOK, 256>>>(qkvh, 3 * D, D, rms_k1, kb, SSELF, rcos, rsin);
    {
        dim3 tb(32, 8), tg(SSELF / 32, HDIM / 32, BH);
        vtrans_kernel<<<tg, tb>>>(qkvh, 3 * D, 2 * D, vb, SSELF);
    }
    // logits = scale * q k^T -> fp16 (softmax in place)
    gemm(qb, kb, nullptr, Pb, SSELF, SSELF, HDIM, HDIM, HDIM, SSELF,
         NH * uQ, uQ, NH * uQ, uQ, NH * uL, uL, NH, BH,
         nullptr, scale, 0, nullptr, nullptr, nullptr, 0);
    softmax_kernel<<<BH * SSELF, 256>>>(Pb, SSELF);
    // attn = P @ V -> fp16 merged [TOK, D]
    gemm(Pb, vb, nullptr, ab, SSELF, HDIM, SSELF, SSELF, SSELF, D,
         NH * uL, uL, NH * uV, uV, (long long)SSELF * D, HDIM, NH, BH,
         nullptr, 1.f, 0, nullptr, nullptr, nullptr, 0);
    // h1 = h + gate_sa * (attn W_o1^T + b)
    gemm(ab, wo1, ph1, nullptr, TOK, D, D, D, D, D,
         0,0,0,0,0,0,1,1, b_o1, 1.f, 2, h, sst, temb, 2);
    // x2 = LN(h1)
    ln_kernel<<<TOK, 256>>>(ph1, xb, ln2_g, ln2_b, nullptr, nullptr, 0, 0, SSELF);
    // q2lin -> fp16
    gemm(xb, wq2, nullptr, qkvh, TOK, D, D, D, D, D,
         0,0,0,0,0,0,1,1, b_q2, 1.f, 0, nullptr, nullptr, nullptr, 0);
    rms_heads_kernel<<<TOK, 256>>>(qkvh, D, 0, rms_q2, qb, SSELF, nullptr, nullptr);
    // kv2 = enc @ w_kv2^T + b -> fp16
    gemm(encb, wkv2, nullptr, kv2h, TOKC, 2 * D, D, D, D, 2 * D,
         0,0,0,0,0,0,1,1, b_kv2, 1.f, 0, nullptr, nullptr, nullptr, 0);
    rms_heads_kernel<<<TOKC, 256>>>(kv2h, 2 * D, 0, rms_k2, kb, SCROSS, nullptr, nullptr);
    {
        dim3 tb(32, 8), tg(SCROSS / 32, HDIM / 32, BH);
        vtrans_kernel<<<tg, tb>>>(kv2h, 2 * D, D, vb, SCROSS);
    }
    // logits2 -> fp16
    gemm(qb, kb, nullptr, Pb, SSELF, SCROSS, HDIM, HDIM, HDIM, SCROSS,
         NH * uQ, uQ, NH * uK2, uK2, NH * uL2, uL2, NH, BH,
         nullptr, scale, 0, nullptr, nullptr, nullptr, 0);
    softmax_kernel<<<BH * SSELF, 256>>>(Pb, SCROSS);
    // attn2
    gemm(Pb, vb, nullptr, ab, SSELF, HDIM, SCROSS, SCROSS, SCROSS, D,
         NH * uL2, uL2, NH * uV2, uV2, (long long)SSELF * D, HDIM, NH, BH,
         nullptr, 1.f, 0, nullptr, nullptr, nullptr, 0);
    // h2 = h1 + attn2 W_o2^T + b
    gemm(ab, wo2, ph2, nullptr, TOK, D, D, D, D, D,
         0,0,0,0,0,0,1,1, b_o2, 1.f, 3, ph1, nullptr, nullptr, 0);
    // xff
    ln_kernel<<<TOK, 256>>>(ph2, xb, nullptr, nullptr, sst, temb, 3, 4, SSELF);
    // mid = gelu(xff W_ff1^T + b) -> fp16
    gemm(xb, wff1, nullptr, mb, TOK, FFND, D, D, D, FFND,
         0,0,0,0,0,0,1,1, b_ff1, 1.f, 1, nullptr, nullptr, nullptr, 0);
    // out = h2 + gate_ff * (mid W_ff2^T + b)
    gemm(mb, wff2, out, nullptr, TOK, D, FFND, FFND, FFND, D,
         0,0,0,0,0,0,1,1, b_ff2, 1.f, 2, ph2, sst, temb, 5);

    (void)in_sizes; (void)n_in; (void)out_size;
}

// round 12
// speedup vs baseline: 1.3070x; 1.0194x over previous
#include <cuda_runtime.h>
#include <cuda_fp16.h>
#include <cstdint>
#include <math.h>

// ---------------- problem constants ----------------
#define D      2560
#define SSELF  2048
#define SCROSS 512
#define NB     2
#define NH     20
#define HDIM   128
#define FFND   10240
#define TOK    4096
#define TOKC   1024
#define BH     40
#define EPSV   1e-6f

typedef __half f16;

// ---------------- scratch (device globals) ----------------
__device__ float g_h1  [(size_t)TOK * D];
__device__ float g_h2  [(size_t)TOK * D];

__device__ f16 g_qkvh[(size_t)TOK * 3 * D];
__device__ f16 g_kv2h[(size_t)TOKC * 2 * D];
__device__ f16 g_x[(size_t)TOK * D];
__device__ f16 g_q[(size_t)TOK * D];
__device__ f16 g_a[(size_t)TOK * D];
__device__ f16 g_m[(size_t)TOK * FFND];
__device__ f16 g_P[(size_t)BH * SSELF * SSELF];
__device__ f16 g_enc[(size_t)TOKC * D];
__device__ f16 g_kb[(size_t)TOK * D];
__device__ f16 g_vb[(size_t)TOK * D];
__device__ f16 g_wqkv[(size_t)3 * D * D];
__device__ f16 g_wo1 [(size_t)D * D];
__device__ f16 g_wq2 [(size_t)D * D];
__device__ f16 g_wkv2[(size_t)2 * D * D];
__device__ f16 g_wo2 [(size_t)D * D];
__device__ f16 g_wff1[(size_t)FFND * D];
__device__ f16 g_wff2[(size_t)D * FFND];

// ---------------- small helpers ----------------
__device__ __forceinline__ float fast_gelu(float x) {
    float u = 0.7978845608028654f * (x + 0.044715f * x * x * x);
    float t = 1.0f - 2.0f / (1.0f + __expf(2.0f * u));
    return 0.5f * x * (1.0f + t);
}

__device__ __forceinline__ uint32_t h2_bits(__half2 h) {
    uint32_t u;
    memcpy(&u, &h, 4);
    return u;
}

__device__ __forceinline__ uint32_t smem_u32(const void* p) {
    uint32_t a;
    asm("{ .reg .u64 t; cvta.to.shared.u64 t, %1; cvt.u32.u64 %0, t; }" : "=r"(a) : "l"(p));
    return a;
}

#define CP_ASYNC16(dst, src) \
    asm volatile("cp.async.cg.shared.global [%0], [%1], 16;" :: "r"(dst), "l"(src))
#define CP_COMMIT() asm volatile("cp.async.commit_group;" ::: "memory")
#define CP_WAIT1()  asm volatile("cp.async.wait_group 1;" ::: "memory")

__device__ __forceinline__ void ldsm4(uint32_t* r, uint32_t addr) {
    asm volatile("ldmatrix.sync.aligned.m8n8.x4.shared.b16 {%0,%1,%2,%3}, [%4];"
        : "=r"(r[0]), "=r"(r[1]), "=r"(r[2]), "=r"(r[3]) : "r"(addr));
}

__device__ __forceinline__ void mma16816h(float* c, const uint32_t* a, const uint32_t* b) {
    asm volatile("mma.sync.aligned.m16n8k16.row.col.f32.f16.f16.f32 "
        "{%0,%1,%2,%3}, {%4,%5,%6,%7}, {%8,%9}, {%0,%1,%2,%3};"
        : "+f"(c[0]), "+f"(c[1]), "+f"(c[2]), "+f"(c[3])
        : "r"(a[0]), "r"(a[1]), "r"(a[2]), "r"(a[3]), "r"(b[0]), "r"(b[1]));
}

// ---------------- reductions ----------------
__device__ __forceinline__ float blockReduceSum(float v) {
    __shared__ float sh[32];
    int lane = threadIdx.x & 31, wid = threadIdx.x >> 5;
    #pragma unroll
    for (int o = 16; o > 0; o >>= 1) v += __shfl_xor_sync(0xffffffffu, v, o);
    __syncthreads();
    if (lane == 0) sh[wid] = v;
    __syncthreads();
    int nw = blockDim.x >> 5;
    float r = (threadIdx.x < nw) ? sh[threadIdx.x] : 0.0f;
    if (wid == 0) {
        #pragma unroll
        for (int o = 16; o > 0; o >>= 1) r += __shfl_xor_sync(0xffffffffu, r, o);
        if (lane == 0) sh[0] = r;
    }
    __syncthreads();
    return sh[0];
}

__device__ __forceinline__ float blockReduceMax(float v) {
    __shared__ float sh[32];
    int lane = threadIdx.x & 31, wid = threadIdx.x >> 5;
    #pragma unroll
    for (int o = 16; o > 0; o >>= 1) v = fmaxf(v, __shfl_xor_sync(0xffffffffu, v, o));
    __syncthreads();
    if (lane == 0) sh[wid] = v;
    __syncthreads();
    int nw = blockDim.x >> 5;
    float r = (threadIdx.x < nw) ? sh[threadIdx.x] : -3.4e38f;
    if (wid == 0) {
        #pragma unroll
        for (int o = 16; o > 0; o >>= 1) r = fmaxf(r, __shfl_xor_sync(0xffffffffu, r, o));
        if (lane == 0) sh[0] = r;
    }
    __syncthreads();
    return sh[0];
}

// ---------------- elementwise producers ----------------
__global__ void __launch_bounds__(256) ln_kernel(
    const float* __restrict__ in, f16* __restrict__ ob,
    const float* __restrict__ gamma, const float* __restrict__ beta,
    const float* __restrict__ sst, const float* __restrict__ temb,
    int iShift, int iScale, int rowsPerB)
{
    long long r = blockIdx.x;
    const float* x = in + r * D;
    float s1 = 0.f, s2 = 0.f;
    for (int d = threadIdx.x; d < D; d += 256) { float v = x[d]; s1 += v; s2 += v * v; }
    s1 = blockReduceSum(s1);
    s2 = blockReduceSum(s2);
    float mean = s1 * (1.0f / D);
    float var  = s2 * (1.0f / D) - mean * mean;
    float rstd = rsqrtf(var + EPSV);
    int b = (int)(r / rowsPerB);
    for (int d = threadIdx.x; d < D; d += 256) {
        float y = (x[d] - mean) * rstd;
        if (sst) {
            float sc = sst[iScale * D + d] + temb[((long long)b * 6 + iScale) * D + d];
            float sh = sst[iShift * D + d] + temb[((long long)b * 6 + iShift) * D + d];
            y = y * (1.f + sc) + sh;
        } else if (gamma) {
            y = y * gamma[d] + beta[d];
        }
        ob[r * D + d] = __float2half_rn(y);
    }
}

__global__ void __launch_bounds__(256) rms_heads_kernel(
    const f16* __restrict__ in, int ldin, int off,
    const float* __restrict__ w, f16* __restrict__ ob, int Srows,
    const float* __restrict__ rcos, const float* __restrict__ rsin)
{
    long long r = blockIdx.x;
    int b = (int)(r / Srows), s = (int)(r % Srows);
    const f16* x = in + r * ldin + off;
    float s2 = 0.f;
    for (int d = threadIdx.x; d < D; d += 256) { float v = __half2float(x[d]); s2 += v * v; }
    s2 = blockReduceSum(s2);
    float rms = rsqrtf(s2 * (1.0f / D) + EPSV);
    for (int d = threadIdx.x; d < D; d += 256) {
        int h = d >> 7, dd = d & 127;
        float v = __half2float(x[d]) * rms * w[d];
        if (rcos) {
            int pd = (dd < 64) ? d + 64 : d - 64;
            float vp = __half2float(x[pd]) * rms * w[pd];
            float c = rcos[s * HDIM + dd], sn = rsin[s * HDIM + dd];
            v = (dd < 64) ? (v * c - vp * sn) : (v * c + vp * sn);
        }
        ob[(((long long)(b * NH + h)) * Srows + s) * HDIM + dd] = __float2half_rn(v);
    }
}

__global__ void vtrans_kernel(
    const f16* __restrict__ in, int ldin, int off,
    f16* __restrict__ out, int Srows)
{
    __shared__ f16 tile[32][33];
    int bz = blockIdx.z;
    int b = bz / NH, h = bz % NH;
    int s0 = blockIdx.x * 32, d0 = blockIdx.y * 32;
    int tx = threadIdx.x, ty = threadIdx.y;
    int colBase = off + h * HDIM + d0;
    #pragma unroll
    for (int i = 0; i < 4; i++) {
        int s = s0 + ty + i * 8;
        tile[ty + i * 8][tx] = in[(long long)(b * Srows + s) * ldin + colBase + tx];
    }
    __syncthreads();
    #pragma unroll
    for (int i = 0; i < 4; i++) {
        int d = d0 + ty + i * 8;
        out[((long long)bz * HDIM + d) * Srows + s0 + tx] = tile[tx][ty + i * 8];
    }
}

__global__ void __launch_bounds__(256) softmax_kernel(f16* __restrict__ p, int len)
{
    long long r = blockIdx.x;
    f16* x = p + r * (long long)len;
    int nper = len >> 8;
    float xv[8];
    float mx = -3.4e38f;
    for (int i = 0; i < nper; i++) {
        xv[i] = __half2float(x[threadIdx.x + (i << 8)]);
        mx = fmaxf(mx, xv[i]);
    }
    mx = blockReduceMax(mx);
    float sum = 0.f;
    for (int i = 0; i < nper; i++) { xv[i] = __expf(xv[i] - mx); sum += xv[i]; }
    sum = blockReduceSum(sum);
    float inv = 1.0f / sum;
    for (int i = 0; i < nper; i++)
        x[threadIdx.x + (i << 8)] = __float2half_rn(xv[i] * inv);
}

__global__ void __launch_bounds__(256) conv_kernel(
    const float* __restrict__ in, f16* __restrict__ ob, long long n)
{
    long long n8 = n >> 3;
    const float4* in4 = (const float4*)in;
    uint4* o4 = (uint4*)ob;
    for (long long i = blockIdx.x * 256LL + threadIdx.x; i < n8; i += (long long)gridDim.x * 256) {
        float4 a = in4[2 * i], b = in4[2 * i + 1];
        uint4 o;
        o.x = h2_bits(__floats2half2_rn(a.x, a.y));
        o.y = h2_bits(__floats2half2_rn(a.z, a.w));
        o.z = h2_bits(__floats2half2_rn(b.x, b.y));
        o.w = h2_bits(__floats2half2_rn(b.z, b.w));
        o4[i] = o;
    }
}

// ---------------- fp16 single-product GEMM, 64x64 warp tiles, BK=64 ----------------
// BM=BN=128, BK=64 (128-byte rows), 4 warps (2x2 of 64x64), 3-stage cp.async, 2 CTAs/SM
// inner loop: B-frags first, then per-M-row A-ldsm feeding 8 MMAs (LDS/tensor overlap)
#define STAGE_BYTES 32768
#define OFF_A 0
#define OFF_B 16384
#define NSTAGE 3
#define GEMM_SMEM (NSTAGE * STAGE_BYTES)

// 128-byte rows, 8 x 16B chunks, XOR-8 swizzle
__device__ __forceinline__ uint32_t tswz(int row, int chunk) {
    return (uint32_t)(row * 128 + ((chunk ^ (row & 7)) << 4));
}

__global__ void __launch_bounds__(128, 2) gemm_h1_kernel(
    const f16* __restrict__ A, const f16* __restrict__ B,
    float* __restrict__ C, f16* __restrict__ Cf,
    int K, int lda, int ldb, int ldc,
    long long sAo, long long sAi, long long sBo, long long sBi,
    long long sCo, long long sCi, int innerN,
    const float* __restrict__ bias, float alpha, int mode,
    const float* __restrict__ res,
    const float* __restrict__ sst, const float* __restrict__ temb,
    int modIdx)
{
    extern __shared__ char smem[];
    uint32_t sbase = smem_u32(smem);
    int tid = threadIdx.x, wid = tid >> 5, lane = tid & 31;

    int bi = blockIdx.z;
    long long aBase = (long long)(bi / innerN) * sAo + (long long)(bi % innerN) * sAi;
    long long bBase = (long long)(bi / innerN) * sBo + (long long)(bi % innerN) * sBi;
    long long cBase = (long long)(bi / innerN) * sCo + (long long)(bi % innerN) * sCi;
    int m0 = blockIdx.y * 128, n0 = blockIdx.x * 128;

    const f16* Ap = A + aBase + (long long)m0 * lda;
    const f16* Bp = B + bBase + (long long)n0 * ldb;

    int lrow = tid >> 3, lch = tid & 7;
    int NC = K >> 6;

    auto load_stage = [&](int c) {
        int s = c % NSTAGE;
        uint32_t st = sbase + s * STAGE_BYTES;
        int k0 = c << 6;
        #pragma unroll
        for (int q = 0; q < 8; q++) {
            int row = lrow + q * 16;
            uint32_t sw = tswz(row, lch);
            long long gk = k0 + lch * 8;
            CP_ASYNC16(st + OFF_A + sw, Ap + (long long)row * lda + gk);
            CP_ASYNC16(st + OFF_B + sw, Bp + (long long)row * ldb + gk);
        }
    };

    float acc[4][8][4];
    #pragma unroll
    for (int i = 0; i < 4; i++)
        #pragma unroll
        for (int j = 0; j < 8; j++)
            #pragma unroll
            for (int e = 0; e < 4; e++) acc[i][j][e] = 0.f;

    int wm = (wid >> 1) * 64, wn = (wid & 1) * 64;

    load_stage(0); CP_COMMIT();
    if (NC > 1) load_stage(1);
    CP_COMMIT();

    for (int c = 0; c < NC; c++) {
        int s = c % NSTAGE;
        CP_WAIT1();
        __syncthreads();
        if (c + 2 < NC) load_stage(c + 2);
        CP_COMMIT();

        uint32_t st = sbase + s * STAGE_BYTES;
        #pragma unroll
        for (int kk = 0; kk < 4; kk++) {
            uint32_t bfr[8][2];
            int rB = (lane & 7) + ((lane >> 4) << 3);
            int cB = (kk << 1) + ((lane >> 3) & 1);
            #pragma unroll
            for (int ntp = 0; ntp < 4; ntp++) {
                uint32_t t[4];
                ldsm4(t, st + OFF_B + tswz(wn + ntp * 16 + rB, cB));
                bfr[2*ntp][0]=t[0]; bfr[2*ntp][1]=t[1]; bfr[2*ntp+1][0]=t[2]; bfr[2*ntp+1][1]=t[3];
            }
            int rA = lane & 15, cA = (kk << 1) + (lane >> 4);
            #pragma unroll
            for (int mt = 0; mt < 4; mt++) {
                uint32_t ah[4];
                ldsm4(ah, st + OFF_A + tswz(wm + mt * 16 + rA, cA));
                #pragma unroll
                for (int nt = 0; nt < 8; nt++)
                    mma16816h(acc[mt][nt], ah, bfr[nt]);
            }
        }
    }

    // ---- epilogue ----
    int qrow = lane >> 2, qcol = (lane & 3) * 2;
    #pragma unroll
    for (int mt = 0; mt < 4; mt++) {
        #pragma unroll
        for (int nt = 0; nt < 8; nt++) {
            #pragma unroll
            for (int e = 0; e < 4; e++) {
                long long rrow = m0 + wm + mt * 16 + qrow + ((e >> 1) ? 8 : 0);
                int col = n0 + wn + nt * 8 + qcol + (e & 1);
                float v = acc[mt][nt][e] * alpha;
                if (bias) v += bias[col];
                if (mode == 1) v = fast_gelu(v);
                long long ci = cBase + rrow * ldc + col;
                if (mode == 2) {
                    int b_ = (int)(rrow >> 11);
                    float g = sst[(long long)modIdx * D + col] +
                              temb[((long long)b_ * 6 + modIdx) * D + col];
                    v = res[ci] + g * v;
                } else if (mode == 3) {
                    v = res[ci] + v;
                }
                if (C)  C[ci]  = v;
                if (Cf) Cf[ci] = __float2half_rn(v);
            }
        }
    }
}

// ---------------- host launch helper ----------------
static void gemm(const f16* A, const f16* B, float* C, f16* Cf,
                 int M, int N, int K, int lda, int ldb, int ldc,
                 long long sAo, long long sAi, long long sBo, long long sBi,
                 long long sCo, long long sCi, int innerN, int nbatch,
                 const float* bias, float alpha, int mode,
                 const float* res, const float* sst, const float* temb,
                 int modIdx)
{
    dim3 grid(N / 128, M / 128, nbatch), block(128);
    gemm_h1_kernel<<<grid, block, GEMM_SMEM>>>(
        A, B, C, Cf, K, lda, ldb, ldc,
        sAo, sAi, sBo, sBi, sCo, sCi, innerN,
        bias, alpha, mode, res, sst, temb, modIdx);
}

#define GETP(sym) ({ void* _p; cudaGetSymbolAddress(&_p, sym); _p; })

extern "C" void kernel_launch(void* const* d_in, const int* in_sizes, int n_in,
                              void* d_out, int out_size)
{
    const float* h    = (const float*)d_in[0];
    const float* enc  = (const float*)d_in[1];
    const float* temb = (const float*)d_in[2];
    const float* rcos = (const float*)d_in[3];
    const float* rsin = (const float*)d_in[4];
    const float* sst  = (const float*)d_in[5];
    const float* w_qkv = (const float*)d_in[6];
    const float* b_qkv = (const float*)d_in[7];
    const float* rms_q1 = (const float*)d_in[8];
    const float* rms_k1 = (const float*)d_in[9];
    const float* w_o1 = (const float*)d_in[10];
    const float* b_o1 = (const float*)d_in[11];
    const float* ln2_g = (const float*)d_in[12];
    const float* ln2_b = (const float*)d_in[13];
    const float* w_q2 = (const float*)d_in[14];
    const float* b_q2 = (const float*)d_in[15];
    const float* w_kv2 = (const float*)d_in[16];
    const float* b_kv2 = (const float*)d_in[17];
    const float* rms_q2 = (const float*)d_in[18];
    const float* rms_k2 = (const float*)d_in[19];
    const float* w_o2 = (const float*)d_in[20];
    const float* b_o2 = (const float*)d_in[21];
    const float* w_ff1 = (const float*)d_in[22];
    const float* b_ff1 = (const float*)d_in[23];
    const float* w_ff2 = (const float*)d_in[24];
    const float* b_ff2 = (const float*)d_in[25];
    float* out = (float*)d_out;

    cudaFuncSetAttribute(gemm_h1_kernel, cudaFuncAttributeMaxDynamicSharedMemorySize, GEMM_SMEM);

    float* ph1  = (float*)GETP(g_h1);
    float* ph2  = (float*)GETP(g_h2);
    f16 *qkvh=(f16*)GETP(g_qkvh);
    f16 *kv2h=(f16*)GETP(g_kv2h);
    f16 *xb=(f16*)GETP(g_x);
    f16 *qb=(f16*)GETP(g_q);
    f16 *ab=(f16*)GETP(g_a);
    f16 *mb=(f16*)GETP(g_m);
    f16 *Pb=(f16*)GETP(g_P);
    f16 *encb=(f16*)GETP(g_enc);
    f16 *kb=(f16*)GETP(g_kb), *vb=(f16*)GETP(g_vb);
    f16 *wqkv=(f16*)GETP(g_wqkv);
    f16 *wo1=(f16*)GETP(g_wo1);
    f16 *wq2=(f16*)GETP(g_wq2);
    f16 *wkv2=(f16*)GETP(g_wkv2);
    f16 *wo2=(f16*)GETP(g_wo2);
    f16 *wff1=(f16*)GETP(g_wff1);
    f16 *wff2=(f16*)GETP(g_wff2);

    const float scale = 0.08838834764831845f;
    const long long uQ  = (long long)SSELF * HDIM;
    const long long uL  = (long long)SSELF * SSELF;
    const long long uV  = (long long)HDIM * SSELF;
    const long long uK2 = (long long)SCROSS * HDIM;
    const long long uL2 = (long long)SSELF * SCROSS;
    const long long uV2 = (long long)HDIM * SCROSS;

    // 0) ln ; 1) conv wqkv ; 2) conv wo1 ; 3) qkv GEMM (profiled = idx 3)
    ln_kernel<<<TOK, 256>>>(h, xb, nullptr, nullptr, sst, temb, 0, 1, SSELF);
    conv_kernel<<<1024, 256>>>(w_qkv, wqkv, (long long)3 * D * D);
    conv_kernel<<<512, 256>>>(w_o1, wo1, (long long)D * D);
    gemm(xb, wqkv, nullptr, qkvh, TOK, 3 * D, D, D, D, 3 * D,
         0,0,0,0,0,0,1,1, b_qkv, 1.f, 0, nullptr, nullptr, nullptr, 0);
    // other converts
    conv_kernel<<<512, 256>>>(w_q2,  wq2,  (long long)D * D);
    conv_kernel<<<512, 256>>>(w_kv2, wkv2, (long long)2 * D * D);
    conv_kernel<<<512, 256>>>(w_o2,  wo2,  (long long)D * D);
    conv_kernel<<<1024, 256>>>(w_ff1, wff1, (long long)FFND * D);
    conv_kernel<<<1024, 256>>>(w_ff2, wff2, (long long)D * FFND);
    conv_kernel<<<512, 256>>>(enc,  encb, (long long)TOKC * D);
    // heads
    rms_heads_kernel<<<TOK, 256>>>(qkvh, 3 * D, 0, rms_q1, qb, SSELF, rcos, rsin);
    rms_heads_kernel<<<TOK, 256>>>(qkvh, 3 * D, D, rms_k1, kb, SSELF, rcos, rsin);
    {
        dim3 tb(32, 8), tg(SSELF / 32, HDIM / 32, BH);
        vtrans_kernel<<<tg, tb>>>(qkvh, 3 * D, 2 * D, vb, SSELF);
    }
    // logits = scale * q k^T -> fp16 (softmax in place)
    gemm(qb, kb, nullptr, Pb, SSELF, SSELF, HDIM, HDIM, HDIM, SSELF,
         NH * uQ, uQ, NH * uQ, uQ, NH * uL, uL, NH, BH,
         nullptr, scale, 0, nullptr, nullptr, nullptr, 0);
    softmax_kernel<<<BH * SSELF, 256>>>(Pb, SSELF);
    // attn = P @ V -> fp16 merged [TOK, D]
    gemm(Pb, vb, nullptr, ab, SSELF, HDIM, SSELF, SSELF, SSELF, D,
         NH * uL, uL, NH * uV, uV, (long long)SSELF * D, HDIM, NH, BH,
         nullptr, 1.f, 0, nullptr, nullptr, nullptr, 0);
    // h1 = h + gate_sa * (attn W_o1^T + b)
    gemm(ab, wo1, ph1, nullptr, TOK, D, D, D, D, D,
         0,0,0,0,0,0,1,1, b_o1, 1.f, 2, h, sst, temb, 2);
    // x2 = LN(h1)
    ln_kernel<<<TOK, 256>>>(ph1, xb, ln2_g, ln2_b, nullptr, nullptr, 0, 0, SSELF);
    // q2lin -> fp16
    gemm(xb, wq2, nullptr, qkvh, TOK, D, D, D, D, D,
         0,0,0,0,0,0,1,1, b_q2, 1.f, 0, nullptr, nullptr, nullptr, 0);
    rms_heads_kernel<<<TOK, 256>>>(qkvh, D, 0, rms_q2, qb, SSELF, nullptr, nullptr);
    // kv2 = enc @ w_kv2^T + b -> fp16
    gemm(encb, wkv2, nullptr, kv2h, TOKC, 2 * D, D, D, D, 2 * D,
         0,0,0,0,0,0,1,1, b_kv2, 1.f, 0, nullptr, nullptr, nullptr, 0);
    rms_heads_kernel<<<TOKC, 256>>>(kv2h, 2 * D, 0, rms_k2, kb, SCROSS, nullptr, nullptr);
    {
        dim3 tb(32, 8), tg(SCROSS / 32, HDIM / 32, BH);
        vtrans_kernel<<<tg, tb>>>(kv2h, 2 * D, D, vb, SCROSS);
    }
    // logits2 -> fp16
    gemm(qb, kb, nullptr, Pb, SSELF, SCROSS, HDIM, HDIM, HDIM, SCROSS,
         NH * uQ, uQ, NH * uK2, uK2, NH * uL2, uL2, NH, BH,
         nullptr, scale, 0, nullptr, nullptr, nullptr, 0);
    softmax_kernel<<<BH * SSELF, 256>>>(Pb, SCROSS);
    // attn2
    gemm(Pb, vb, nullptr, ab, SSELF, HDIM, SCROSS, SCROSS, SCROSS, D,
         NH * uL2, uL2, NH * uV2, uV2, (long long)SSELF * D, HDIM, NH, BH,
         nullptr, 1.f, 0, nullptr, nullptr, nullptr, 0);
    // h2 = h1 + attn2 W_o2^T + b
    gemm(ab, wo2, ph2, nullptr, TOK, D, D, D, D, D,
         0,0,0,0,0,0,1,1, b_o2, 1.f, 3, ph1, nullptr, nullptr, 0);
    // xff
    ln_kernel<<<TOK, 256>>>(ph2, xb, nullptr, nullptr, sst, temb, 3, 4, SSELF);
    // mid = gelu(xff W_ff1^T + b) -> fp16
    gemm(xb, wff1, nullptr, mb, TOK, FFND, D, D, D, FFND,
         0,0,0,0,0,0,1,1, b_ff1, 1.f, 1, nullptr, nullptr, nullptr, 0);
    // out = h2 + gate_ff * (mid W_ff2^T + b)
    gemm(mb, wff2, out, nullptr, TOK, D, FFND, FFND, FFND, D,
         0,0,0,0,0,0,1,1, b_ff2, 1.f, 2, ph2, sst, temb, 5);

    (void)in_sizes; (void)n_in; (void)out_size;
}

// round 13
// speedup vs baseline: 1.5780x; 1.2073x over previous
#include <cuda_runtime.h>
#include <cuda_fp16.h>
#include <cstdint>
#include <math.h>

// ---------------- problem constants ----------------
#define D      2560
#define SSELF  2048
#define SCROSS 512
#define NB     2
#define NH     20
#define HDIM   128
#define FFND   10240
#define TOK    4096
#define TOKC   1024
#define BH     40
#define EPSV   1e-6f

typedef __half f16;

// ---------------- scratch (device globals) ----------------
__device__ float g_h1  [(size_t)TOK * D];
__device__ float g_h2  [(size_t)TOK * D];

__device__ f16 g_qkvh[(size_t)TOK * 3 * D];
__device__ f16 g_kv2h[(size_t)TOKC * 2 * D];
__device__ f16 g_x[(size_t)TOK * D];
__device__ f16 g_q[(size_t)TOK * D];
__device__ f16 g_a[(size_t)TOK * D];
__device__ f16 g_m[(size_t)TOK * FFND];
__device__ f16 g_enc[(size_t)TOKC * D];
__device__ f16 g_kb[(size_t)TOK * D];
__device__ f16 g_vb[(size_t)TOK * D];
__device__ f16 g_wqkv[(size_t)3 * D * D];
__device__ f16 g_wo1 [(size_t)D * D];
__device__ f16 g_wq2 [(size_t)D * D];
__device__ f16 g_wkv2[(size_t)2 * D * D];
__device__ f16 g_wo2 [(size_t)D * D];
__device__ f16 g_wff1[(size_t)FFND * D];
__device__ f16 g_wff2[(size_t)D * FFND];

// ---------------- small helpers ----------------
__device__ __forceinline__ float fast_gelu(float x) {
    float u = 0.7978845608028654f * (x + 0.044715f * x * x * x);
    float t = 1.0f - 2.0f / (1.0f + __expf(2.0f * u));
    return 0.5f * x * (1.0f + t);
}

__device__ __forceinline__ uint32_t h2_bits(__half2 h) {
    uint32_t u;
    memcpy(&u, &h, 4);
    return u;
}

__device__ __forceinline__ uint32_t smem_u32(const void* p) {
    uint32_t a;
    asm("{ .reg .u64 t; cvta.to.shared.u64 t, %1; cvt.u32.u64 %0, t; }" : "=r"(a) : "l"(p));
    return a;
}

#define CP_ASYNC16(dst, src) \
    asm volatile("cp.async.cg.shared.global [%0], [%1], 16;" :: "r"(dst), "l"(src))
#define CP_COMMIT() asm volatile("cp.async.commit_group;" ::: "memory")
#define CP_WAIT1()  asm volatile("cp.async.wait_group 1;" ::: "memory")
#define CP_WAIT2()  asm volatile("cp.async.wait_group 2;" ::: "memory")

__device__ __forceinline__ void ldsm4(uint32_t* r, uint32_t addr) {
    asm volatile("ldmatrix.sync.aligned.m8n8.x4.shared.b16 {%0,%1,%2,%3}, [%4];"
        : "=r"(r[0]), "=r"(r[1]), "=r"(r[2]), "=r"(r[3]) : "r"(addr));
}

__device__ __forceinline__ void mma16816h(float* c, const uint32_t* a, const uint32_t* b) {
    asm volatile("mma.sync.aligned.m16n8k16.row.col.f32.f16.f16.f32 "
        "{%0,%1,%2,%3}, {%4,%5,%6,%7}, {%8,%9}, {%0,%1,%2,%3};"
        : "+f"(c[0]), "+f"(c[1]), "+f"(c[2]), "+f"(c[3])
        : "r"(a[0]), "r"(a[1]), "r"(a[2]), "r"(a[3]), "r"(b[0]), "r"(b[1]));
}

// 128-byte rows, 8 x 16B chunks, XOR-8 swizzle
__device__ __forceinline__ uint32_t tswz(int row, int chunk) {
    return (uint32_t)(row * 128 + ((chunk ^ (row & 7)) << 4));
}
// 256-byte rows, 16 chunks; XOR low 3 bits of chunk with row
__device__ __forceinline__ uint32_t tswz2(int row, int chunk) {
    return (uint32_t)(row * 256 + (((chunk & 8) | ((chunk ^ row) & 7)) << 4));
}

// ---------------- reductions ----------------
__device__ __forceinline__ float blockReduceSum(float v) {
    __shared__ float sh[32];
    int lane = threadIdx.x & 31, wid = threadIdx.x >> 5;
    #pragma unroll
    for (int o = 16; o > 0; o >>= 1) v += __shfl_xor_sync(0xffffffffu, v, o);
    __syncthreads();
    if (lane == 0) sh[wid] = v;
    __syncthreads();
    int nw = blockDim.x >> 5;
    float r = (threadIdx.x < nw) ? sh[threadIdx.x] : 0.0f;
    if (wid == 0) {
        #pragma unroll
        for (int o = 16; o > 0; o >>= 1) r += __shfl_xor_sync(0xffffffffu, r, o);
        if (lane == 0) sh[0] = r;
    }
    __syncthreads();
    return sh[0];
}

// ---------------- elementwise producers ----------------
__global__ void __launch_bounds__(256) ln_kernel(
    const float* __restrict__ in, f16* __restrict__ ob,
    const float* __restrict__ gamma, const float* __restrict__ beta,
    const float* __restrict__ sst, const float* __restrict__ temb,
    int iShift, int iScale, int rowsPerB)
{
    long long r = blockIdx.x;
    const float* x = in + r * D;
    float s1 = 0.f, s2 = 0.f;
    for (int d = threadIdx.x; d < D; d += 256) { float v = x[d]; s1 += v; s2 += v * v; }
    s1 = blockReduceSum(s1);
    s2 = blockReduceSum(s2);
    float mean = s1 * (1.0f / D);
    float var  = s2 * (1.0f / D) - mean * mean;
    float rstd = rsqrtf(var + EPSV);
    int b = (int)(r / rowsPerB);
    for (int d = threadIdx.x; d < D; d += 256) {
        float y = (x[d] - mean) * rstd;
        if (sst) {
            float sc = sst[iScale * D + d] + temb[((long long)b * 6 + iScale) * D + d];
            float sh = sst[iShift * D + d] + temb[((long long)b * 6 + iShift) * D + d];
            y = y * (1.f + sc) + sh;
        } else if (gamma) {
            y = y * gamma[d] + beta[d];
        }
        ob[r * D + d] = __float2half_rn(y);
    }
}

// RMS + optional rope, with output scale (bakes attention 1/sqrt(d) into q)
__global__ void __launch_bounds__(256) rms_heads_kernel(
    const f16* __restrict__ in, int ldin, int off,
    const float* __restrict__ w, f16* __restrict__ ob, int Srows,
    const float* __restrict__ rcos, const float* __restrict__ rsin, float outScale)
{
    long long r = blockIdx.x;
    int b = (int)(r / Srows), s = (int)(r % Srows);
    const f16* x = in + r * ldin + off;
    float s2 = 0.f;
    for (int d = threadIdx.x; d < D; d += 256) { float v = __half2float(x[d]); s2 += v * v; }
    s2 = blockReduceSum(s2);
    float rms = rsqrtf(s2 * (1.0f / D) + EPSV);
    for (int d = threadIdx.x; d < D; d += 256) {
        int h = d >> 7, dd = d & 127;
        float v = __half2float(x[d]) * rms * w[d];
        if (rcos) {
            int pd = (dd < 64) ? d + 64 : d - 64;
            float vp = __half2float(x[pd]) * rms * w[pd];
            float c = rcos[s * HDIM + dd], sn = rsin[s * HDIM + dd];
            v = (dd < 64) ? (v * c - vp * sn) : (v * c + vp * sn);
        }
        ob[(((long long)(b * NH + h)) * Srows + s) * HDIM + dd] = __float2half_rn(v * outScale);
    }
}

__global__ void vtrans_kernel(
    const f16* __restrict__ in, int ldin, int off,
    f16* __restrict__ out, int Srows)
{
    __shared__ f16 tile[32][33];
    int bz = blockIdx.z;
    int b = bz / NH, h = bz % NH;
    int s0 = blockIdx.x * 32, d0 = blockIdx.y * 32;
    int tx = threadIdx.x, ty = threadIdx.y;
    int colBase = off + h * HDIM + d0;
    #pragma unroll
    for (int i = 0; i < 4; i++) {
        int s = s0 + ty + i * 8;
        tile[ty + i * 8][tx] = in[(long long)(b * Srows + s) * ldin + colBase + tx];
    }
    __syncthreads();
    #pragma unroll
    for (int i = 0; i < 4; i++) {
        int d = d0 + ty + i * 8;
        out[((long long)bz * HDIM + d) * Srows + s0 + tx] = tile[tx][ty + i * 8];
    }
}

__global__ void __launch_bounds__(256) conv_kernel(
    const float* __restrict__ in, f16* __restrict__ ob, long long n)
{
    long long n8 = n >> 3;
    const float4* in4 = (const float4*)in;
    uint4* o4 = (uint4*)ob;
    for (long long i = blockIdx.x * 256LL + threadIdx.x; i < n8; i += (long long)gridDim.x * 256) {
        float4 a = in4[2 * i], b = in4[2 * i + 1];
        uint4 o;
        o.x = h2_bits(__floats2half2_rn(a.x, a.y));
        o.y = h2_bits(__floats2half2_rn(a.z, a.w));
        o.z = h2_bits(__floats2half2_rn(b.x, b.y));
        o.w = h2_bits(__floats2half2_rn(b.z, b.w));
        o4[i] = o;
    }
}

// ---------------- flash attention ----------------
// grid (Sq/128, BH), block 256 (8 warps x 16 q rows).
// Q [BH, Sq, HD] (scale baked in), K [BH, Skv, HD], Vt [BH, HD, Skv]
// out: merged [b*Sq + q, h*HD + d] fp16
#define FA_NSTAGE 3
#define FA_QBYTES 32768
#define FA_SMEM   (FA_QBYTES + FA_NSTAGE * 32768)

__global__ void __launch_bounds__(256, 1) flash_kernel(
    const f16* __restrict__ Q, const f16* __restrict__ Kt, const f16* __restrict__ Vt,
    f16* __restrict__ Out, int Skv)
{
    extern __shared__ char smem[];
    uint32_t sbase = smem_u32(smem);
    int tid = threadIdx.x, wid = tid >> 5, lane = tid & 31;
    int q0 = blockIdx.x * 128;
    int bz = blockIdx.y;
    int b = bz / NH, hh = bz % NH;

    const f16* Qp = Q  + ((long long)bz * SSELF + q0) * HDIM;
    const f16* Kp = Kt + (long long)bz * Skv * HDIM;
    const f16* Vp = Vt + (long long)bz * HDIM * Skv;

    int NT = Skv >> 6;

    // Q load: 128 rows x 16 chunks (group 0)
    {
        int row = tid >> 1, cb = (tid & 1) * 8;
        #pragma unroll
        for (int i = 0; i < 8; i++)
            CP_ASYNC16(sbase + tswz2(row, cb + i), Qp + (long long)row * HDIM + (cb + i) * 8);
    }
    CP_COMMIT();

    auto load_kv = [&](int c) {
        int s = c % FA_NSTAGE;
        uint32_t stK = sbase + FA_QBYTES + s * 32768;
        uint32_t stV = stK + 16384;
        int k0 = c << 6;
        {   // K: 64 rows x 16 chunks
            int row = tid >> 2, cb = (tid & 3) * 4;
            #pragma unroll
            for (int i = 0; i < 4; i++)
                CP_ASYNC16(stK + tswz2(row, cb + i), Kp + (long long)(k0 + row) * HDIM + (cb + i) * 8);
        }
        {   // V^T: 128 rows (d) x 8 chunks (64 keys)
            int row = tid >> 1, cb = (tid & 1) * 4;
            #pragma unroll
            for (int i = 0; i < 4; i++)
                CP_ASYNC16(stV + tswz(row, cb + i), Vp + (long long)row * Skv + k0 + (cb + i) * 8);
        }
    };

    load_kv(0); CP_COMMIT();
    if (NT > 1) load_kv(1);
    CP_COMMIT();

    CP_WAIT2();           // Q ready
    __syncthreads();
    uint32_t qf[8][4];
    {
        int rA = lane & 15, wq = wid * 16;
        #pragma unroll
        for (int ks = 0; ks < 8; ks++)
            ldsm4(qf[ks], sbase + tswz2(wq + rA, ks * 2 + (lane >> 4)));
    }

    float Oa[16][4];
    #pragma unroll
    for (int i = 0; i < 16; i++)
        #pragma unroll
        for (int e = 0; e < 4; e++) Oa[i][e] = 0.f;
    float m0 = -1e30f, m1 = -1e30f, l0 = 0.f, l1 = 0.f;

    int rB = (lane & 7) + ((lane >> 4) << 3);

    for (int c = 0; c < NT; c++) {
        int s = c % FA_NSTAGE;
        CP_WAIT1();
        __syncthreads();
        if (c + 2 < NT) load_kv(c + 2);
        CP_COMMIT();

        uint32_t stK = sbase + FA_QBYTES + s * 32768;
        uint32_t stV = stK + 16384;

        // ---- S = Q K^T (64 keys) ----
        float Sa[8][4];
        #pragma unroll
        for (int i = 0; i < 8; i++)
            #pragma unroll
            for (int e = 0; e < 4; e++) Sa[i][e] = 0.f;
        #pragma unroll
        for (int ks = 0; ks < 8; ks++) {
            int cB = ks * 2 + ((lane >> 3) & 1);
            #pragma unroll
            for (int ntp = 0; ntp < 4; ntp++) {
                uint32_t t[4];
                ldsm4(t, stK + tswz2(ntp * 16 + rB, cB));
                mma16816h(Sa[2 * ntp],     qf[ks], t);
                mma16816h(Sa[2 * ntp + 1], qf[ks], t + 2);
            }
        }

        // ---- online softmax ----
        float tm0 = -1e30f, tm1 = -1e30f;
        #pragma unroll
        for (int nt = 0; nt < 8; nt++) {
            tm0 = fmaxf(tm0, fmaxf(Sa[nt][0], Sa[nt][1]));
            tm1 = fmaxf(tm1, fmaxf(Sa[nt][2], Sa[nt][3]));
        }
        tm0 = fmaxf(tm0, __shfl_xor_sync(0xffffffffu, tm0, 1));
        tm0 = fmaxf(tm0, __shfl_xor_sync(0xffffffffu, tm0, 2));
        tm1 = fmaxf(tm1, __shfl_xor_sync(0xffffffffu, tm1, 1));
        tm1 = fmaxf(tm1, __shfl_xor_sync(0xffffffffu, tm1, 2));
        float nm0 = fmaxf(m0, tm0), nm1 = fmaxf(m1, tm1);
        float cr0 = __expf(m0 - nm0), cr1 = __expf(m1 - nm1);
        m0 = nm0; m1 = nm1;
        float ls0 = 0.f, ls1 = 0.f;
        #pragma unroll
        for (int nt = 0; nt < 8; nt++) {
            Sa[nt][0] = __expf(Sa[nt][0] - m0);
            Sa[nt][1] = __expf(Sa[nt][1] - m0);
            Sa[nt][2] = __expf(Sa[nt][2] - m1);
            Sa[nt][3] = __expf(Sa[nt][3] - m1);
            ls0 += Sa[nt][0] + Sa[nt][1];
            ls1 += Sa[nt][2] + Sa[nt][3];
        }
        l0 = l0 * cr0 + ls0;
        l1 = l1 * cr1 + ls1;
        #pragma unroll
        for (int nt = 0; nt < 16; nt++) {
            Oa[nt][0] *= cr0; Oa[nt][1] *= cr0;
            Oa[nt][2] *= cr1; Oa[nt][3] *= cr1;
        }

        // ---- P fragments + P V ----
        uint32_t pf[4][4];
        #pragma unroll
        for (int j = 0; j < 4; j++) {
            pf[j][0] = h2_bits(__floats2half2_rn(Sa[2 * j][0],     Sa[2 * j][1]));
            pf[j][1] = h2_bits(__floats2half2_rn(Sa[2 * j][2],     Sa[2 * j][3]));
            pf[j][2] = h2_bits(__floats2half2_rn(Sa[2 * j + 1][0], Sa[2 * j + 1][1]));
            pf[j][3] = h2_bits(__floats2half2_rn(Sa[2 * j + 1][2], Sa[2 * j + 1][3]));
        }
        #pragma unroll
        for (int j = 0; j < 4; j++) {
            int cV = j * 2 + ((lane >> 3) & 1);
            #pragma unroll
            for (int ntp = 0; ntp < 8; ntp++) {
                uint32_t t[4];
                ldsm4(t, stV + tswz(ntp * 16 + rB, cV));
                mma16816h(Oa[2 * ntp],     pf[j], t);
                mma16816h(Oa[2 * ntp + 1], pf[j], t + 2);
            }
        }
    }

    // ---- finalize ----
    l0 += __shfl_xor_sync(0xffffffffu, l0, 1);
    l0 += __shfl_xor_sync(0xffffffffu, l0, 2);
    l1 += __shfl_xor_sync(0xffffffffu, l1, 1);
    l1 += __shfl_xor_sync(0xffffffffu, l1, 2);
    float inv0 = 1.0f / l0, inv1 = 1.0f / l1;
    int row0 = q0 + wid * 16 + (lane >> 2);
    int colB = hh * HDIM + (lane & 3) * 2;
    #pragma unroll
    for (int nt = 0; nt < 16; nt++) {
        int col = colB + nt * 8;
        long long i0 = ((long long)(b * SSELF + row0)) * D + col;
        long long i1 = ((long long)(b * SSELF + row0 + 8)) * D + col;
        Out[i0]     = __float2half_rn(Oa[nt][0] * inv0);
        Out[i0 + 1] = __float2half_rn(Oa[nt][1] * inv0);
        Out[i1]     = __float2half_rn(Oa[nt][2] * inv1);
        Out[i1 + 1] = __float2half_rn(Oa[nt][3] * inv1);
    }
}

// ---------------- fp16 single-product GEMM (weight GEMMs) ----------------
#define STAGE_BYTES 32768
#define OFF_A 0
#define OFF_B 16384
#define NSTAGE 3
#define GEMM_SMEM (NSTAGE * STAGE_BYTES)

__global__ void __launch_bounds__(128, 2) gemm_h1_kernel(
    const f16* __restrict__ A, const f16* __restrict__ B,
    float* __restrict__ C, f16* __restrict__ Cf,
    int K, int lda, int ldb, int ldc,
    const float* __restrict__ bias, float alpha, int mode,
    const float* __restrict__ res,
    const float* __restrict__ sst, const float* __restrict__ temb,
    int modIdx)
{
    extern __shared__ char smem[];
    uint32_t sbase = smem_u32(smem);
    int tid = threadIdx.x, wid = tid >> 5, lane = tid & 31;

    int m0 = blockIdx.y * 128, n0 = blockIdx.x * 128;
    const f16* Ap = A + (long long)m0 * lda;
    const f16* Bp = B + (long long)n0 * ldb;

    int lrow = tid >> 3, lch = tid & 7;
    int NC = K >> 6;

    auto load_stage = [&](int c) {
        int s = c % NSTAGE;
        uint32_t st = sbase + s * STAGE_BYTES;
        int k0 = c << 6;
        #pragma unroll
        for (int q = 0; q < 8; q++) {
            int row = lrow + q * 16;
            uint32_t sw = tswz(row, lch);
            long long gk = k0 + lch * 8;
            CP_ASYNC16(st + OFF_A + sw, Ap + (long long)row * lda + gk);
            CP_ASYNC16(st + OFF_B + sw, Bp + (long long)row * ldb + gk);
        }
    };

    float acc[4][8][4];
    #pragma unroll
    for (int i = 0; i < 4; i++)
        #pragma unroll
        for (int j = 0; j < 8; j++)
            #pragma unroll
            for (int e = 0; e < 4; e++) acc[i][j][e] = 0.f;

    int wm = (wid >> 1) * 64, wn = (wid & 1) * 64;

    load_stage(0); CP_COMMIT();
    if (NC > 1) load_stage(1);
    CP_COMMIT();

    for (int c = 0; c < NC; c++) {
        int s = c % NSTAGE;
        CP_WAIT1();
        __syncthreads();
        if (c + 2 < NC) load_stage(c + 2);
        CP_COMMIT();

        uint32_t st = sbase + s * STAGE_BYTES;
        #pragma unroll
        for (int kk = 0; kk < 4; kk++) {
            uint32_t bfr[8][2];
            int rB = (lane & 7) + ((lane >> 4) << 3);
            int cB = (kk << 1) + ((lane >> 3) & 1);
            #pragma unroll
            for (int ntp = 0; ntp < 4; ntp++) {
                uint32_t t[4];
                ldsm4(t, st + OFF_B + tswz(wn + ntp * 16 + rB, cB));
                bfr[2*ntp][0]=t[0]; bfr[2*ntp][1]=t[1]; bfr[2*ntp+1][0]=t[2]; bfr[2*ntp+1][1]=t[3];
            }
            int rA = lane & 15, cA = (kk << 1) + (lane >> 4);
            #pragma unroll
            for (int mt = 0; mt < 4; mt++) {
                uint32_t ah[4];
                ldsm4(ah, st + OFF_A + tswz(wm + mt * 16 + rA, cA));
                #pragma unroll
                for (int nt = 0; nt < 8; nt++)
                    mma16816h(acc[mt][nt], ah, bfr[nt]);
            }
        }
    }

    int qrow = lane >> 2, qcol = (lane & 3) * 2;
    #pragma unroll
    for (int mt = 0; mt < 4; mt++) {
        #pragma unroll
        for (int nt = 0; nt < 8; nt++) {
            #pragma unroll
            for (int e = 0; e < 4; e++) {
                long long rrow = m0 + wm + mt * 16 + qrow + ((e >> 1) ? 8 : 0);
                int col = n0 + wn + nt * 8 + qcol + (e & 1);
                float v = acc[mt][nt][e] * alpha;
                if (bias) v += bias[col];
                if (mode == 1) v = fast_gelu(v);
                long long ci = rrow * (long long)ldc + col;
                if (mode == 2) {
                    int b_ = (int)(rrow >> 11);
                    float g = sst[(long long)modIdx * D + col] +
                              temb[((long long)b_ * 6 + modIdx) * D + col];
                    v = res[ci] + g * v;
                } else if (mode == 3) {
                    v = res[ci] + v;
                }
                if (C)  C[ci]  = v;
                if (Cf) Cf[ci] = __float2half_rn(v);
            }
        }
    }
}

// ---------------- host launch helper ----------------
static void gemm(const f16* A, const f16* B, float* C, f16* Cf,
                 int M, int N, int K, int lda, int ldb, int ldc,
                 const float* bias, float alpha, int mode,
                 const float* res, const float* sst, const float* temb,
                 int modIdx)
{
    dim3 grid(N / 128, M / 128, 1), block(128);
    gemm_h1_kernel<<<grid, block, GEMM_SMEM>>>(
        A, B, C, Cf, K, lda, ldb, ldc,
        bias, alpha, mode, res, sst, temb, modIdx);
}

#define GETP(sym) ({ void* _p; cudaGetSymbolAddress(&_p, sym); _p; })

extern "C" void kernel_launch(void* const* d_in, const int* in_sizes, int n_in,
                              void* d_out, int out_size)
{
    const float* h    = (const float*)d_in[0];
    const float* enc  = (const float*)d_in[1];
    const float* temb = (const float*)d_in[2];
    const float* rcos = (const float*)d_in[3];
    const float* rsin = (const float*)d_in[4];
    const float* sst  = (const float*)d_in[5];
    const float* w_qkv = (const float*)d_in[6];
    const float* b_qkv = (const float*)d_in[7];
    const float* rms_q1 = (const float*)d_in[8];
    const float* rms_k1 = (const float*)d_in[9];
    const float* w_o1 = (const float*)d_in[10];
    const float* b_o1 = (const float*)d_in[11];
    const float* ln2_g = (const float*)d_in[12];
    const float* ln2_b = (const float*)d_in[13];
    const float* w_q2 = (const float*)d_in[14];
    const float* b_q2 = (const float*)d_in[15];
    const float* w_kv2 = (const float*)d_in[16];
    const float* b_kv2 = (const float*)d_in[17];
    const float* rms_q2 = (const float*)d_in[18];
    const float* rms_k2 = (const float*)d_in[19];
    const float* w_o2 = (const float*)d_in[20];
    const float* b_o2 = (const float*)d_in[21];
    const float* w_ff1 = (const float*)d_in[22];
    const float* b_ff1 = (const float*)d_in[23];
    const float* w_ff2 = (const float*)d_in[24];
    const float* b_ff2 = (const float*)d_in[25];
    float* out = (float*)d_out;

    cudaFuncSetAttribute(gemm_h1_kernel, cudaFuncAttributeMaxDynamicSharedMemorySize, GEMM_SMEM);
    cudaFuncSetAttribute(flash_kernel,  cudaFuncAttributeMaxDynamicSharedMemorySize, FA_SMEM);

    float* ph1  = (float*)GETP(g_h1);
    float* ph2  = (float*)GETP(g_h2);
    f16 *qkvh=(f16*)GETP(g_qkvh);
    f16 *kv2h=(f16*)GETP(g_kv2h);
    f16 *xb=(f16*)GETP(g_x);
    f16 *qb=(f16*)GETP(g_q);
    f16 *ab=(f16*)GETP(g_a);
    f16 *mb=(f16*)GETP(g_m);
    f16 *encb=(f16*)GETP(g_enc);
    f16 *kb=(f16*)GETP(g_kb), *vb=(f16*)GETP(g_vb);
    f16 *wqkv=(f16*)GETP(g_wqkv);
    f16 *wo1=(f16*)GETP(g_wo1);
    f16 *wq2=(f16*)GETP(g_wq2);
    f16 *wkv2=(f16*)GETP(g_wkv2);
    f16 *wo2=(f16*)GETP(g_wo2);
    f16 *wff1=(f16*)GETP(g_wff1);
    f16 *wff2=(f16*)GETP(g_wff2);

    const float scale = 0.08838834764831845f;

    // 0) ln ; 1) conv wqkv ; 2) conv wo1 ; 3) qkv GEMM (profiled = idx 3)
    ln_kernel<<<TOK, 256>>>(h, xb, nullptr, nullptr, sst, temb, 0, 1, SSELF);
    conv_kernel<<<1024, 256>>>(w_qkv, wqkv, (long long)3 * D * D);
    conv_kernel<<<512, 256>>>(w_o1, wo1, (long long)D * D);
    gemm(xb, wqkv, nullptr, qkvh, TOK, 3 * D, D, D, D, 3 * D,
         b_qkv, 1.f, 0, nullptr, nullptr, nullptr, 0);
    // other converts
    conv_kernel<<<512, 256>>>(w_q2,  wq2,  (long long)D * D);
    conv_kernel<<<512, 256>>>(w_kv2, wkv2, (long long)2 * D * D);
    conv_kernel<<<512, 256>>>(w_o2,  wo2,  (long long)D * D);
    conv_kernel<<<1024, 256>>>(w_ff1, wff1, (long long)FFND * D);
    conv_kernel<<<1024, 256>>>(w_ff2, wff2, (long long)D * FFND);
    conv_kernel<<<512, 256>>>(enc,  encb, (long long)TOKC * D);
    // heads: q scaled by 1/sqrt(d), k unit
    rms_heads_kernel<<<TOK, 256>>>(qkvh, 3 * D, 0, rms_q1, qb, SSELF, rcos, rsin, scale);
    rms_heads_kernel<<<TOK, 256>>>(qkvh, 3 * D, D, rms_k1, kb, SSELF, rcos, rsin, 1.f);
    {
        dim3 tb(32, 8), tg(SSELF / 32, HDIM / 32, BH);
        vtrans_kernel<<<tg, tb>>>(qkvh, 3 * D, 2 * D, vb, SSELF);
    }
    // flash self-attention -> ab
    flash_kernel<<<dim3(SSELF / 128, BH), 256, FA_SMEM>>>(qb, kb, vb, ab, SSELF);
    // h1 = h + gate_sa * (attn W_o1^T + b)
    gemm(ab, wo1, ph1, nullptr, TOK, D, D, D, D, D,
         b_o1, 1.f, 2, h, sst, temb, 2);
    // x2 = LN(h1)
    ln_kernel<<<TOK, 256>>>(ph1, xb, ln2_g, ln2_b, nullptr, nullptr, 0, 0, SSELF);
    // q2lin -> fp16
    gemm(xb, wq2, nullptr, qkvh, TOK, D, D, D, D, D,
         b_q2, 1.f, 0, nullptr, nullptr, nullptr, 0);
    rms_heads_kernel<<<TOK, 256>>>(qkvh, D, 0, rms_q2, qb, SSELF, nullptr, nullptr, scale);
    // kv2 = enc @ w_kv2^T + b -> fp16
    gemm(encb, wkv2, nullptr, kv2h, TOKC, 2 * D, D, D, D, 2 * D,
         b_kv2, 1.f, 0, nullptr, nullptr, nullptr, 0);
    rms_heads_kernel<<<TOKC, 256>>>(kv2h, 2 * D, 0, rms_k2, kb, SCROSS, nullptr, nullptr, 1.f);
    {
        dim3 tb(32, 8), tg(SCROSS / 32, HDIM / 32, BH);
        vtrans_kernel<<<tg, tb>>>(kv2h, 2 * D, D, vb, SCROSS);
    }
    // flash cross-attention -> ab
    flash_kernel<<<dim3(SSELF / 128, BH), 256, FA_SMEM>>>(qb, kb, vb, ab, SCROSS);
    // h2 = h1 + attn2 W_o2^T + b
    gemm(ab, wo2, ph2, nullptr, TOK, D, D, D, D, D,
         b_o2, 1.f, 3, ph1, nullptr, nullptr, 0);
    // xff
    ln_kernel<<<TOK, 256>>>(ph2, xb, nullptr, nullptr, sst, temb, 3, 4, SSELF);
    // mid = gelu(xff W_ff1^T + b) -> fp16
    gemm(xb, wff1, nullptr, mb, TOK, FFND, D, D, D, FFND,
         b_ff1, 1.f, 1, nullptr, nullptr, nullptr, 0);
    // out = h2 + gate_ff * (mid W_ff2^T + b)
    gemm(mb, wff2, out, nullptr, TOK, D, FFND, FFND, FFND, D,
         b_ff2, 1.f, 2, ph2, sst, temb, 5);

    (void)in_sizes; (void)n_in; (void)out_size;
}

// round 14
// speedup vs baseline: 1.6076x; 1.0187x over previous
#include <cuda_runtime.h>
#include <cuda_fp16.h>
#include <cstdint>
#include <math.h>

// ---------------- problem constants ----------------
#define D      2560
#define SSELF  2048
#define SCROSS 512
#define NB     2
#define NH     20
#define HDIM   128
#define FFND   10240
#define TOK    4096
#define TOKC   1024
#define BH     40
#define EPSV   1e-6f

typedef __half f16;

// ---------------- scratch (device globals) ----------------
__device__ float g_h1  [(size_t)TOK * D];
__device__ float g_h2  [(size_t)TOK * D];

__device__ f16 g_qkvh[(size_t)TOK * 3 * D];
__device__ f16 g_kv2h[(size_t)TOKC * 2 * D];
__device__ f16 g_x[(size_t)TOK * D];
__device__ f16 g_q[(size_t)TOK * D];
__device__ f16 g_a[(size_t)TOK * D];
__device__ f16 g_m[(size_t)TOK * FFND];
__device__ f16 g_enc[(size_t)TOKC * D];
__device__ f16 g_kb[(size_t)TOK * D];
__device__ f16 g_vb[(size_t)TOK * D];
__device__ f16 g_wqkv[(size_t)3 * D * D];
__device__ f16 g_wo1 [(size_t)D * D];
__device__ f16 g_wq2 [(size_t)D * D];
__device__ f16 g_wkv2[(size_t)2 * D * D];
__device__ f16 g_wo2 [(size_t)D * D];
__device__ f16 g_wff1[(size_t)FFND * D];
__device__ f16 g_wff2[(size_t)D * FFND];

// ---------------- small helpers ----------------
__device__ __forceinline__ float fast_gelu(float x) {
    float u = 0.7978845608028654f * (x + 0.044715f * x * x * x);
    float t = 1.0f - 2.0f / (1.0f + __expf(2.0f * u));
    return 0.5f * x * (1.0f + t);
}

__device__ __forceinline__ uint32_t h2_bits(__half2 h) {
    uint32_t u;
    memcpy(&u, &h, 4);
    return u;
}

__device__ __forceinline__ uint32_t smem_u32(const void* p) {
    uint32_t a;
    asm("{ .reg .u64 t; cvta.to.shared.u64 t, %1; cvt.u32.u64 %0, t; }" : "=r"(a) : "l"(p));
    return a;
}

#define CP_ASYNC16(dst, src) \
    asm volatile("cp.async.cg.shared.global [%0], [%1], 16;" :: "r"(dst), "l"(src))
#define CP_COMMIT() asm volatile("cp.async.commit_group;" ::: "memory")
#define CP_WAIT1()  asm volatile("cp.async.wait_group 1;" ::: "memory")
#define CP_WAIT2()  asm volatile("cp.async.wait_group 2;" ::: "memory")

__device__ __forceinline__ void ldsm4(uint32_t* r, uint32_t addr) {
    asm volatile("ldmatrix.sync.aligned.m8n8.x4.shared.b16 {%0,%1,%2,%3}, [%4];"
        : "=r"(r[0]), "=r"(r[1]), "=r"(r[2]), "=r"(r[3]) : "r"(addr));
}

__device__ __forceinline__ void mma16816h(float* c, const uint32_t* a, const uint32_t* b) {
    asm volatile("mma.sync.aligned.m16n8k16.row.col.f32.f16.f16.f32 "
        "{%0,%1,%2,%3}, {%4,%5,%6,%7}, {%8,%9}, {%0,%1,%2,%3};"
        : "+f"(c[0]), "+f"(c[1]), "+f"(c[2]), "+f"(c[3])
        : "r"(a[0]), "r"(a[1]), "r"(a[2]), "r"(a[3]), "r"(b[0]), "r"(b[1]));
}

// 128-byte rows, 8 x 16B chunks, XOR-8 swizzle
__device__ __forceinline__ uint32_t tswz(int row, int chunk) {
    return (uint32_t)(row * 128 + ((chunk ^ (row & 7)) << 4));
}
// 256-byte rows, 16 chunks; XOR low 3 bits of chunk with row
__device__ __forceinline__ uint32_t tswz2(int row, int chunk) {
    return (uint32_t)(row * 256 + (((chunk & 8) | ((chunk ^ row) & 7)) << 4));
}

// ---------------- reductions ----------------
__device__ __forceinline__ float blockReduceSum(float v) {
    __shared__ float sh[32];
    int lane = threadIdx.x & 31, wid = threadIdx.x >> 5;
    #pragma unroll
    for (int o = 16; o > 0; o >>= 1) v += __shfl_xor_sync(0xffffffffu, v, o);
    __syncthreads();
    if (lane == 0) sh[wid] = v;
    __syncthreads();
    int nw = blockDim.x >> 5;
    float r = (threadIdx.x < nw) ? sh[threadIdx.x] : 0.0f;
    if (wid == 0) {
        #pragma unroll
        for (int o = 16; o > 0; o >>= 1) r += __shfl_xor_sync(0xffffffffu, r, o);
        if (lane == 0) sh[0] = r;
    }
    __syncthreads();
    return sh[0];
}

// ---------------- elementwise producers ----------------
__global__ void __launch_bounds__(256) ln_kernel(
    const float* __restrict__ in, f16* __restrict__ ob,
    const float* __restrict__ gamma, const float* __restrict__ beta,
    const float* __restrict__ sst, const float* __restrict__ temb,
    int iShift, int iScale, int rowsPerB)
{
    long long r = blockIdx.x;
    const float* x = in + r * D;
    float s1 = 0.f, s2 = 0.f;
    for (int d = threadIdx.x; d < D; d += 256) { float v = x[d]; s1 += v; s2 += v * v; }
    s1 = blockReduceSum(s1);
    s2 = blockReduceSum(s2);
    float mean = s1 * (1.0f / D);
    float var  = s2 * (1.0f / D) - mean * mean;
    float rstd = rsqrtf(var + EPSV);
    int b = (int)(r / rowsPerB);
    for (int d = threadIdx.x; d < D; d += 256) {
        float y = (x[d] - mean) * rstd;
        if (sst) {
            float sc = sst[iScale * D + d] + temb[((long long)b * 6 + iScale) * D + d];
            float sh = sst[iShift * D + d] + temb[((long long)b * 6 + iShift) * D + d];
            y = y * (1.f + sc) + sh;
        } else if (gamma) {
            y = y * gamma[d] + beta[d];
        }
        ob[r * D + d] = __float2half_rn(y);
    }
}

__global__ void __launch_bounds__(256) rms_heads_kernel(
    const f16* __restrict__ in, int ldin, int off,
    const float* __restrict__ w, f16* __restrict__ ob, int Srows,
    const float* __restrict__ rcos, const float* __restrict__ rsin, float outScale)
{
    long long r = blockIdx.x;
    int b = (int)(r / Srows), s = (int)(r % Srows);
    const f16* x = in + r * ldin + off;
    float s2 = 0.f;
    for (int d = threadIdx.x; d < D; d += 256) { float v = __half2float(x[d]); s2 += v * v; }
    s2 = blockReduceSum(s2);
    float rms = rsqrtf(s2 * (1.0f / D) + EPSV);
    for (int d = threadIdx.x; d < D; d += 256) {
        int h = d >> 7, dd = d & 127;
        float v = __half2float(x[d]) * rms * w[d];
        if (rcos) {
            int pd = (dd < 64) ? d + 64 : d - 64;
            float vp = __half2float(x[pd]) * rms * w[pd];
            float c = rcos[s * HDIM + dd], sn = rsin[s * HDIM + dd];
            v = (dd < 64) ? (v * c - vp * sn) : (v * c + vp * sn);
        }
        ob[(((long long)(b * NH + h)) * Srows + s) * HDIM + dd] = __float2half_rn(v * outScale);
    }
}

__global__ void vtrans_kernel(
    const f16* __restrict__ in, int ldin, int off,
    f16* __restrict__ out, int Srows)
{
    __shared__ f16 tile[32][33];
    int bz = blockIdx.z;
    int b = bz / NH, h = bz % NH;
    int s0 = blockIdx.x * 32, d0 = blockIdx.y * 32;
    int tx = threadIdx.x, ty = threadIdx.y;
    int colBase = off + h * HDIM + d0;
    #pragma unroll
    for (int i = 0; i < 4; i++) {
        int s = s0 + ty + i * 8;
        tile[ty + i * 8][tx] = in[(long long)(b * Srows + s) * ldin + colBase + tx];
    }
    __syncthreads();
    #pragma unroll
    for (int i = 0; i < 4; i++) {
        int d = d0 + ty + i * 8;
        out[((long long)bz * HDIM + d) * Srows + s0 + tx] = tile[tx][ty + i * 8];
    }
}

__global__ void __launch_bounds__(256) conv_kernel(
    const float* __restrict__ in, f16* __restrict__ ob, long long n)
{
    long long n8 = n >> 3;
    const float4* in4 = (const float4*)in;
    uint4* o4 = (uint4*)ob;
    for (long long i = blockIdx.x * 256LL + threadIdx.x; i < n8; i += (long long)gridDim.x * 256) {
        float4 a = in4[2 * i], b = in4[2 * i + 1];
        uint4 o;
        o.x = h2_bits(__floats2half2_rn(a.x, a.y));
        o.y = h2_bits(__floats2half2_rn(a.z, a.w));
        o.z = h2_bits(__floats2half2_rn(b.x, b.y));
        o.w = h2_bits(__floats2half2_rn(b.z, b.w));
        o4[i] = o;
    }
}

// ---------------- flash attention ----------------
#define FA_NSTAGE 3
#define FA_QBYTES 32768
#define FA_SMEM   (FA_QBYTES + FA_NSTAGE * 32768)

__global__ void __launch_bounds__(256, 1) flash_kernel(
    const f16* __restrict__ Q, const f16* __restrict__ Kt, const f16* __restrict__ Vt,
    f16* __restrict__ Out, int Skv)
{
    extern __shared__ char smem[];
    uint32_t sbase = smem_u32(smem);
    int tid = threadIdx.x, wid = tid >> 5, lane = tid & 31;
    int q0 = blockIdx.x * 128;
    int bz = blockIdx.y;
    int b = bz / NH, hh = bz % NH;

    const f16* Qp = Q  + ((long long)bz * SSELF + q0) * HDIM;
    const f16* Kp = Kt + (long long)bz * Skv * HDIM;
    const f16* Vp = Vt + (long long)bz * HDIM * Skv;

    int NT = Skv >> 6;

    {
        int row = tid >> 1, cb = (tid & 1) * 8;
        #pragma unroll
        for (int i = 0; i < 8; i++)
            CP_ASYNC16(sbase + tswz2(row, cb + i), Qp + (long long)row * HDIM + (cb + i) * 8);
    }
    CP_COMMIT();

    auto load_kv = [&](int c) {
        int s = c % FA_NSTAGE;
        uint32_t stK = sbase + FA_QBYTES + s * 32768;
        uint32_t stV = stK + 16384;
        int k0 = c << 6;
        {
            int row = tid >> 2, cb = (tid & 3) * 4;
            #pragma unroll
            for (int i = 0; i < 4; i++)
                CP_ASYNC16(stK + tswz2(row, cb + i), Kp + (long long)(k0 + row) * HDIM + (cb + i) * 8);
        }
        {
            int row = tid >> 1, cb = (tid & 1) * 4;
            #pragma unroll
            for (int i = 0; i < 4; i++)
                CP_ASYNC16(stV + tswz(row, cb + i), Vp + (long long)row * Skv + k0 + (cb + i) * 8);
        }
    };

    load_kv(0); CP_COMMIT();
    if (NT > 1) load_kv(1);
    CP_COMMIT();

    CP_WAIT2();
    __syncthreads();
    uint32_t qf[8][4];
    {
        int rA = lane & 15, wq = wid * 16;
        #pragma unroll
        for (int ks = 0; ks < 8; ks++)
            ldsm4(qf[ks], sbase + tswz2(wq + rA, ks * 2 + (lane >> 4)));
    }

    float Oa[16][4];
    #pragma unroll
    for (int i = 0; i < 16; i++)
        #pragma unroll
        for (int e = 0; e < 4; e++) Oa[i][e] = 0.f;
    float m0 = -1e30f, m1 = -1e30f, l0 = 0.f, l1 = 0.f;

    int rB = (lane & 7) + ((lane >> 4) << 3);

    for (int c = 0; c < NT; c++) {
        int s = c % FA_NSTAGE;
        CP_WAIT1();
        __syncthreads();
        if (c + 2 < NT) load_kv(c + 2);
        CP_COMMIT();

        uint32_t stK = sbase + FA_QBYTES + s * 32768;
        uint32_t stV = stK + 16384;

        float Sa[8][4];
        #pragma unroll
        for (int i = 0; i < 8; i++)
            #pragma unroll
            for (int e = 0; e < 4; e++) Sa[i][e] = 0.f;
        #pragma unroll
        for (int ks = 0; ks < 8; ks++) {
            int cB = ks * 2 + ((lane >> 3) & 1);
            #pragma unroll
            for (int ntp = 0; ntp < 4; ntp++) {
                uint32_t t[4];
                ldsm4(t, stK + tswz2(ntp * 16 + rB, cB));
                mma16816h(Sa[2 * ntp],     qf[ks], t);
                mma16816h(Sa[2 * ntp + 1], qf[ks], t + 2);
            }
        }

        float tm0 = -1e30f, tm1 = -1e30f;
        #pragma unroll
        for (int nt = 0; nt < 8; nt++) {
            tm0 = fmaxf(tm0, fmaxf(Sa[nt][0], Sa[nt][1]));
            tm1 = fmaxf(tm1, fmaxf(Sa[nt][2], Sa[nt][3]));
        }
        tm0 = fmaxf(tm0, __shfl_xor_sync(0xffffffffu, tm0, 1));
        tm0 = fmaxf(tm0, __shfl_xor_sync(0xffffffffu, tm0, 2));
        tm1 = fmaxf(tm1, __shfl_xor_sync(0xffffffffu, tm1, 1));
        tm1 = fmaxf(tm1, __shfl_xor_sync(0xffffffffu, tm1, 2));
        float nm0 = fmaxf(m0, tm0), nm1 = fmaxf(m1, tm1);
        float cr0 = __expf(m0 - nm0), cr1 = __expf(m1 - nm1);
        m0 = nm0; m1 = nm1;
        float ls0 = 0.f, ls1 = 0.f;
        #pragma unroll
        for (int nt = 0; nt < 8; nt++) {
            Sa[nt][0] = __expf(Sa[nt][0] - m0);
            Sa[nt][1] = __expf(Sa[nt][1] - m0);
            Sa[nt][2] = __expf(Sa[nt][2] - m1);
            Sa[nt][3] = __expf(Sa[nt][3] - m1);
            ls0 += Sa[nt][0] + Sa[nt][1];
            ls1 += Sa[nt][2] + Sa[nt][3];
        }
        l0 = l0 * cr0 + ls0;
        l1 = l1 * cr1 + ls1;
        #pragma unroll
        for (int nt = 0; nt < 16; nt++) {
            Oa[nt][0] *= cr0; Oa[nt][1] *= cr0;
            Oa[nt][2] *= cr1; Oa[nt][3] *= cr1;
        }

        uint32_t pf[4][4];
        #pragma unroll
        for (int j = 0; j < 4; j++) {
            pf[j][0] = h2_bits(__floats2half2_rn(Sa[2 * j][0],     Sa[2 * j][1]));
            pf[j][1] = h2_bits(__floats2half2_rn(Sa[2 * j][2],     Sa[2 * j][3]));
            pf[j][2] = h2_bits(__floats2half2_rn(Sa[2 * j + 1][0], Sa[2 * j + 1][1]));
            pf[j][3] = h2_bits(__floats2half2_rn(Sa[2 * j + 1][2], Sa[2 * j + 1][3]));
        }
        #pragma unroll
        for (int j = 0; j < 4; j++) {
            int cV = j * 2 + ((lane >> 3) & 1);
            #pragma unroll
            for (int ntp = 0; ntp < 8; ntp++) {
                uint32_t t[4];
                ldsm4(t, stV + tswz(ntp * 16 + rB, cV));
                mma16816h(Oa[2 * ntp],     pf[j], t);
                mma16816h(Oa[2 * ntp + 1], pf[j], t + 2);
            }
        }
    }

    l0 += __shfl_xor_sync(0xffffffffu, l0, 1);
    l0 += __shfl_xor_sync(0xffffffffu, l0, 2);
    l1 += __shfl_xor_sync(0xffffffffu, l1, 1);
    l1 += __shfl_xor_sync(0xffffffffu, l1, 2);
    float inv0 = 1.0f / l0, inv1 = 1.0f / l1;
    int row0 = q0 + wid * 16 + (lane >> 2);
    int colB = hh * HDIM + (lane & 3) * 2;
    #pragma unroll
    for (int nt = 0; nt < 16; nt++) {
        int col = colB + nt * 8;
        long long i0 = ((long long)(b * SSELF + row0)) * D + col;
        long long i1 = ((long long)(b * SSELF + row0 + 8)) * D + col;
        Out[i0]     = __float2half_rn(Oa[nt][0] * inv0);
        Out[i0 + 1] = __float2half_rn(Oa[nt][1] * inv0);
        Out[i1]     = __float2half_rn(Oa[nt][2] * inv1);
        Out[i1 + 1] = __float2half_rn(Oa[nt][3] * inv1);
    }
}

// ---------------- fp16 GEMM: 2-stage, 3 CTAs/SM ----------------
#define STAGE_BYTES 32768
#define OFF_A 0
#define OFF_B 16384
#define NSTAGE 2
#define GEMM_SMEM (NSTAGE * STAGE_BYTES)

__global__ void __launch_bounds__(128, 3) gemm_h1_kernel(
    const f16* __restrict__ A, const f16* __restrict__ B,
    float* __restrict__ C, f16* __restrict__ Cf,
    int K, int lda, int ldb, int ldc,
    const float* __restrict__ bias, float alpha, int mode,
    const float* __restrict__ res,
    const float* __restrict__ sst, const float* __restrict__ temb,
    int modIdx)
{
    extern __shared__ char smem[];
    uint32_t sbase = smem_u32(smem);
    int tid = threadIdx.x, wid = tid >> 5, lane = tid & 31;

    int m0 = blockIdx.y * 128, n0 = blockIdx.x * 128;
    const f16* Ap = A + (long long)m0 * lda;
    const f16* Bp = B + (long long)n0 * ldb;

    int lrow = tid >> 3, lch = tid & 7;
    int NC = K >> 6;

    auto load_stage = [&](int c) {
        int s = c & 1;
        uint32_t st = sbase + s * STAGE_BYTES;
        int k0 = c << 6;
        #pragma unroll
        for (int q = 0; q < 8; q++) {
            int row = lrow + q * 16;
            uint32_t sw = tswz(row, lch);
            long long gk = k0 + lch * 8;
            CP_ASYNC16(st + OFF_A + sw, Ap + (long long)row * lda + gk);
            CP_ASYNC16(st + OFF_B + sw, Bp + (long long)row * ldb + gk);
        }
    };

    float acc[4][8][4];
    #pragma unroll
    for (int i = 0; i < 4; i++)
        #pragma unroll
        for (int j = 0; j < 8; j++)
            #pragma unroll
            for (int e = 0; e < 4; e++) acc[i][j][e] = 0.f;

    int wm = (wid >> 1) * 64, wn = (wid & 1) * 64;

    load_stage(0); CP_COMMIT();
    if (NC > 1) load_stage(1);
    CP_COMMIT();

    for (int c = 0; c < NC; c++) {
        uint32_t st = sbase + (c & 1) * STAGE_BYTES;
        CP_WAIT1();
        __syncthreads();
        // per-kk: A frags resident, B streamed per-ntp to keep regs low
        #pragma unroll
        for (int kk = 0; kk < 4; kk++) {
            uint32_t af[4][4];
            int rA = lane & 15, cA = (kk << 1) + (lane >> 4);
            #pragma unroll
            for (int mt = 0; mt < 4; mt++)
                ldsm4(af[mt], st + OFF_A + tswz(wm + mt * 16 + rA, cA));
            int rB = (lane & 7) + ((lane >> 4) << 3);
            int cB = (kk << 1) + ((lane >> 3) & 1);
            #pragma unroll
            for (int ntp = 0; ntp < 4; ntp++) {
                uint32_t t[4];
                ldsm4(t, st + OFF_B + tswz(wn + ntp * 16 + rB, cB));
                #pragma unroll
                for (int mt = 0; mt < 4; mt++) {
                    mma16816h(acc[mt][2 * ntp],     af[mt], t);
                    mma16816h(acc[mt][2 * ntp + 1], af[mt], t + 2);
                }
            }
        }
        __syncthreads();
        if (c + 2 < NC) { load_stage(c + 2); CP_COMMIT(); }
    }

    int qrow = lane >> 2, qcol = (lane & 3) * 2;
    #pragma unroll
    for (int mt = 0; mt < 4; mt++) {
        #pragma unroll
        for (int nt = 0; nt < 8; nt++) {
            #pragma unroll
            for (int e = 0; e < 4; e++) {
                long long rrow = m0 + wm + mt * 16 + qrow + ((e >> 1) ? 8 : 0);
                int col = n0 + wn + nt * 8 + qcol + (e & 1);
                float v = acc[mt][nt][e] * alpha;
                if (bias) v += bias[col];
                if (mode == 1) v = fast_gelu(v);
                long long ci = rrow * (long long)ldc + col;
                if (mode == 2) {
                    int b_ = (int)(rrow >> 11);
                    float g = sst[(long long)modIdx * D + col] +
                              temb[((long long)b_ * 6 + modIdx) * D + col];
                    v = res[ci] + g * v;
                } else if (mode == 3) {
                    v = res[ci] + v;
                }
                if (C)  C[ci]  = v;
                if (Cf) Cf[ci] = __float2half_rn(v);
            }
        }
    }
}

// ---------------- host launch helper ----------------
static void gemm(const f16* A, const f16* B, float* C, f16* Cf,
                 int M, int N, int K, int lda, int ldb, int ldc,
                 const float* bias, float alpha, int mode,
                 const float* res, const float* sst, const float* temb,
                 int modIdx)
{
    dim3 grid(N / 128, M / 128, 1), block(128);
    gemm_h1_kernel<<<grid, block, GEMM_SMEM>>>(
        A, B, C, Cf, K, lda, ldb, ldc,
        bias, alpha, mode, res, sst, temb, modIdx);
}

#define GETP(sym) ({ void* _p; cudaGetSymbolAddress(&_p, sym); _p; })

extern "C" void kernel_launch(void* const* d_in, const int* in_sizes, int n_in,
                              void* d_out, int out_size)
{
    const float* h    = (const float*)d_in[0];
    const float* enc  = (const float*)d_in[1];
    const float* temb = (const float*)d_in[2];
    const float* rcos = (const float*)d_in[3];
    const float* rsin = (const float*)d_in[4];
    const float* sst  = (const float*)d_in[5];
    const float* w_qkv = (const float*)d_in[6];
    const float* b_qkv = (const float*)d_in[7];
    const float* rms_q1 = (const float*)d_in[8];
    const float* rms_k1 = (const float*)d_in[9];
    const float* w_o1 = (const float*)d_in[10];
    const float* b_o1 = (const float*)d_in[11];
    const float* ln2_g = (const float*)d_in[12];
    const float* ln2_b = (const float*)d_in[13];
    const float* w_q2 = (const float*)d_in[14];
    const float* b_q2 = (const float*)d_in[15];
    const float* w_kv2 = (const float*)d_in[16];
    const float* b_kv2 = (const float*)d_in[17];
    const float* rms_q2 = (const float*)d_in[18];
    const float* rms_k2 = (const float*)d_in[19];
    const float* w_o2 = (const float*)d_in[20];
    const float* b_o2 = (const float*)d_in[21];
    const float* w_ff1 = (const float*)d_in[22];
    const float* b_ff1 = (const float*)d_in[23];
    const float* w_ff2 = (const float*)d_in[24];
    const float* b_ff2 = (const float*)d_in[25];
    float* out = (float*)d_out;

    cudaFuncSetAttribute(gemm_h1_kernel, cudaFuncAttributeMaxDynamicSharedMemorySize, GEMM_SMEM);
    cudaFuncSetAttribute(flash_kernel,  cudaFuncAttributeMaxDynamicSharedMemorySize, FA_SMEM);

    float* ph1  = (float*)GETP(g_h1);
    float* ph2  = (float*)GETP(g_h2);
    f16 *qkvh=(f16*)GETP(g_qkvh);
    f16 *kv2h=(f16*)GETP(g_kv2h);
    f16 *xb=(f16*)GETP(g_x);
    f16 *qb=(f16*)GETP(g_q);
    f16 *ab=(f16*)GETP(g_a);
    f16 *mb=(f16*)GETP(g_m);
    f16 *encb=(f16*)GETP(g_enc);
    f16 *kb=(f16*)GETP(g_kb), *vb=(f16*)GETP(g_vb);
    f16 *wqkv=(f16*)GETP(g_wqkv);
    f16 *wo1=(f16*)GETP(g_wo1);
    f16 *wq2=(f16*)GETP(g_wq2);
    f16 *wkv2=(f16*)GETP(g_wkv2);
    f16 *wo2=(f16*)GETP(g_wo2);
    f16 *wff1=(f16*)GETP(g_wff1);
    f16 *wff2=(f16*)GETP(g_wff2);

    const float scale = 0.08838834764831845f;

    // 0) ln ; 1) conv wqkv ; 2) conv wo1 ; 3) qkv GEMM (profiled = idx 3)
    ln_kernel<<<TOK, 256>>>(h, xb, nullptr, nullptr, sst, temb, 0, 1, SSELF);
    conv_kernel<<<1024, 256>>>(w_qkv, wqkv, (long long)3 * D * D);
    conv_kernel<<<512, 256>>>(w_o1, wo1, (long long)D * D);
    gemm(xb, wqkv, nullptr, qkvh, TOK, 3 * D, D, D, D, 3 * D,
         b_qkv, 1.f, 0, nullptr, nullptr, nullptr, 0);
    // other converts
    conv_kernel<<<512, 256>>>(w_q2,  wq2,  (long long)D * D);
    conv_kernel<<<512, 256>>>(w_kv2, wkv2, (long long)2 * D * D);
    conv_kernel<<<512, 256>>>(w_o2,  wo2,  (long long)D * D);
    conv_kernel<<<1024, 256>>>(w_ff1, wff1, (long long)FFND * D);
    conv_kernel<<<1024, 256>>>(w_ff2, wff2, (long long)D * FFND);
    conv_kernel<<<512, 256>>>(enc,  encb, (long long)TOKC * D);
    // heads
    rms_heads_kernel<<<TOK, 256>>>(qkvh, 3 * D, 0, rms_q1, qb, SSELF, rcos, rsin, scale);
    rms_heads_kernel<<<TOK, 256>>>(qkvh, 3 * D, D, rms_k1, kb, SSELF, rcos, rsin, 1.f);
    {
        dim3 tb(32, 8), tg(SSELF / 32, HDIM / 32, BH);
        vtrans_kernel<<<tg, tb>>>(qkvh, 3 * D, 2 * D, vb, SSELF);
    }
    // flash self-attention
    flash_kernel<<<dim3(SSELF / 128, BH), 256, FA_SMEM>>>(qb, kb, vb, ab, SSELF);
    // h1 = h + gate_sa * (attn W_o1^T + b)
    gemm(ab, wo1, ph1, nullptr, TOK, D, D, D, D, D,
         b_o1, 1.f, 2, h, sst, temb, 2);
    // x2 = LN(h1)
    ln_kernel<<<TOK, 256>>>(ph1, xb, ln2_g, ln2_b, nullptr, nullptr, 0, 0, SSELF);
    // q2lin
    gemm(xb, wq2, nullptr, qkvh, TOK, D, D, D, D, D,
         b_q2, 1.f, 0, nullptr, nullptr, nullptr, 0);
    rms_heads_kernel<<<TOK, 256>>>(qkvh, D, 0, rms_q2, qb, SSELF, nullptr, nullptr, scale);
    // kv2
    gemm(encb, wkv2, nullptr, kv2h, TOKC, 2 * D, D, D, D, 2 * D,
         b_kv2, 1.f, 0, nullptr, nullptr, nullptr, 0);
    rms_heads_kernel<<<TOKC, 256>>>(kv2h, 2 * D, 0, rms_k2, kb, SCROSS, nullptr, nullptr, 1.f);
    {
        dim3 tb(32, 8), tg(SCROSS / 32, HDIM / 32, BH);
        vtrans_kernel<<<tg, tb>>>(kv2h, 2 * D, D, vb, SCROSS);
    }
    // flash cross-attention
    flash_kernel<<<dim3(SSELF / 128, BH), 256, FA_SMEM>>>(qb, kb, vb, ab, SCROSS);
    // h2 = h1 + attn2 W_o2^T + b
    gemm(ab, wo2, ph2, nullptr, TOK, D, D, D, D, D,
         b_o2, 1.f, 3, ph1, nullptr, nullptr, 0);
    // xff
    ln_kernel<<<TOK, 256>>>(ph2, xb, nullptr, nullptr, sst, temb, 3, 4, SSELF);
    // mid = gelu(xff W_ff1^T + b)
    gemm(xb, wff1, nullptr, mb, TOK, FFND, D, D, D, FFND,
         b_ff1, 1.f, 1, nullptr, nullptr, nullptr, 0);
    // out = h2 + gate_ff * (mid W_ff2^T + b)
    gemm(mb, wff2, out, nullptr, TOK, D, FFND, FFND, FFND, D,
         b_ff2, 1.f, 2, ph2, sst, temb, 5);

    (void)in_sizes; (void)n_in; (void)out_size;
}

// round 15
// speedup vs baseline: 1.6320x; 1.0152x over previous
#include <cuda_runtime.h>
#include <cuda_fp16.h>
#include <cstdint>
#include <math.h>

// ---------------- problem constants ----------------
#define D      2560
#define SSELF  2048
#define SCROSS 512
#define NB     2
#define NH     20
#define HDIM   128
#define FFND   10240
#define TOK    4096
#define TOKC   1024
#define BH     40
#define EPSV   1e-6f

typedef __half f16;

// ---------------- scratch (device globals) ----------------
__device__ float g_h1  [(size_t)TOK * D];
__device__ float g_h2  [(size_t)TOK * D];

__device__ f16 g_qkvh[(size_t)TOK * 3 * D];
__device__ f16 g_kv2h[(size_t)TOKC * 2 * D];
__device__ f16 g_x[(size_t)TOK * D];
__device__ f16 g_q[(size_t)TOK * D];
__device__ f16 g_a[(size_t)TOK * D];
__device__ f16 g_m[(size_t)TOK * FFND];
__device__ f16 g_enc[(size_t)TOKC * D];
__device__ f16 g_kb[(size_t)TOK * D];
__device__ f16 g_vb[(size_t)TOK * D];
__device__ f16 g_wqkv[(size_t)3 * D * D];
__device__ f16 g_wo1 [(size_t)D * D];
__device__ f16 g_wq2 [(size_t)D * D];
__device__ f16 g_wkv2[(size_t)2 * D * D];
__device__ f16 g_wo2 [(size_t)D * D];
__device__ f16 g_wff1[(size_t)FFND * D];
__device__ f16 g_wff2[(size_t)D * FFND];

// ---------------- small helpers ----------------
__device__ __forceinline__ float fast_gelu(float x) {
    float u = 0.7978845608028654f * (x + 0.044715f * x * x * x);
    float t = 1.0f - 2.0f / (1.0f + __expf(2.0f * u));
    return 0.5f * x * (1.0f + t);
}

__device__ __forceinline__ uint32_t h2_bits(__half2 h) {
    uint32_t u;
    memcpy(&u, &h, 4);
    return u;
}

__device__ __forceinline__ uint32_t smem_u32(const void* p) {
    uint32_t a;
    asm("{ .reg .u64 t; cvta.to.shared.u64 t, %1; cvt.u32.u64 %0, t; }" : "=r"(a) : "l"(p));
    return a;
}

#define CP_ASYNC16(dst, src) \
    asm volatile("cp.async.cg.shared.global [%0], [%1], 16;" :: "r"(dst), "l"(src))
#define CP_COMMIT() asm volatile("cp.async.commit_group;" ::: "memory")
#define CP_WAIT1()  asm volatile("cp.async.wait_group 1;" ::: "memory")
#define CP_WAIT2()  asm volatile("cp.async.wait_group 2;" ::: "memory")

__device__ __forceinline__ void ldsm4(uint32_t* r, uint32_t addr) {
    asm volatile("ldmatrix.sync.aligned.m8n8.x4.shared.b16 {%0,%1,%2,%3}, [%4];"
        : "=r"(r[0]), "=r"(r[1]), "=r"(r[2]), "=r"(r[3]) : "r"(addr));
}

__device__ __forceinline__ void mma16816h(float* c, const uint32_t* a, const uint32_t* b) {
    asm volatile("mma.sync.aligned.m16n8k16.row.col.f32.f16.f16.f32 "
        "{%0,%1,%2,%3}, {%4,%5,%6,%7}, {%8,%9}, {%0,%1,%2,%3};"
        : "+f"(c[0]), "+f"(c[1]), "+f"(c[2]), "+f"(c[3])
        : "r"(a[0]), "r"(a[1]), "r"(a[2]), "r"(a[3]), "r"(b[0]), "r"(b[1]));
}

// 128-byte rows, 8 x 16B chunks, XOR-8 swizzle
__device__ __forceinline__ uint32_t tswz(int row, int chunk) {
    return (uint32_t)(row * 128 + ((chunk ^ (row & 7)) << 4));
}
// 256-byte rows, 16 chunks
__device__ __forceinline__ uint32_t tswz2(int row, int chunk) {
    return (uint32_t)(row * 256 + (((chunk & 8) | ((chunk ^ row) & 7)) << 4));
}

// ---------------- reductions ----------------
__device__ __forceinline__ float blockReduceSum(float v) {
    __shared__ float sh[32];
    int lane = threadIdx.x & 31, wid = threadIdx.x >> 5;
    #pragma unroll
    for (int o = 16; o > 0; o >>= 1) v += __shfl_xor_sync(0xffffffffu, v, o);
    __syncthreads();
    if (lane == 0) sh[wid] = v;
    __syncthreads();
    int nw = blockDim.x >> 5;
    float r = (threadIdx.x < nw) ? sh[threadIdx.x] : 0.0f;
    if (wid == 0) {
        #pragma unroll
        for (int o = 16; o > 0; o >>= 1) r += __shfl_xor_sync(0xffffffffu, r, o);
        if (lane == 0) sh[0] = r;
    }
    __syncthreads();
    return sh[0];
}

// ---------------- elementwise producers ----------------
__global__ void __launch_bounds__(256) ln_kernel(
    const float* __restrict__ in, f16* __restrict__ ob,
    const float* __restrict__ gamma, const float* __restrict__ beta,
    const float* __restrict__ sst, const float* __restrict__ temb,
    int iShift, int iScale, int rowsPerB)
{
    long long r = blockIdx.x;
    const float* x = in + r * D;
    float s1 = 0.f, s2 = 0.f;
    for (int d = threadIdx.x; d < D; d += 256) { float v = x[d]; s1 += v; s2 += v * v; }
    s1 = blockReduceSum(s1);
    s2 = blockReduceSum(s2);
    float mean = s1 * (1.0f / D);
    float var  = s2 * (1.0f / D) - mean * mean;
    float rstd = rsqrtf(var + EPSV);
    int b = (int)(r / rowsPerB);
    for (int d = threadIdx.x; d < D; d += 256) {
        float y = (x[d] - mean) * rstd;
        if (sst) {
            float sc = sst[iScale * D + d] + temb[((long long)b * 6 + iScale) * D + d];
            float sh = sst[iShift * D + d] + temb[((long long)b * 6 + iShift) * D + d];
            y = y * (1.f + sc) + sh;
        } else if (gamma) {
            y = y * gamma[d] + beta[d];
        }
        ob[r * D + d] = __float2half_rn(y);
    }
}

// fused q+k rms + rope for self-attention (reads qkv once, shares rope tables)
__global__ void __launch_bounds__(256) rmsqk_kernel(
    const f16* __restrict__ in,               // qkv [TOK, 3D]
    const float* __restrict__ wq, const float* __restrict__ wk,
    f16* __restrict__ oq, f16* __restrict__ ok,
    const float* __restrict__ rcos, const float* __restrict__ rsin, float qscale)
{
    long long r = blockIdx.x;
    int b = (int)(r >> 11), s = (int)(r & 2047);
    const f16* xq = in + r * (3 * D);
    const f16* xk = xq + D;
    float sq = 0.f, sk = 0.f;
    for (int d = threadIdx.x; d < D; d += 256) {
        float vq = __half2float(xq[d]); sq += vq * vq;
        float vk = __half2float(xk[d]); sk += vk * vk;
    }
    sq = blockReduceSum(sq);
    sk = blockReduceSum(sk);
    float rmq = rsqrtf(sq * (1.0f / D) + EPSV);
    float rmk = rsqrtf(sk * (1.0f / D) + EPSV);
    for (int d = threadIdx.x; d < D; d += 256) {
        int h = d >> 7, dd = d & 127;
        int pd = (dd < 64) ? d + 64 : d - 64;
        float c = rcos[s * HDIM + dd], sn = rsin[s * HDIM + dd];
        float vq  = __half2float(xq[d])  * rmq * wq[d];
        float vqp = __half2float(xq[pd]) * rmq * wq[pd];
        float vk  = __half2float(xk[d])  * rmk * wk[d];
        float vkp = __half2float(xk[pd]) * rmk * wk[pd];
        float rq = (dd < 64) ? (vq * c - vqp * sn) : (vq * c + vqp * sn);
        float rk = (dd < 64) ? (vk * c - vkp * sn) : (vk * c + vkp * sn);
        long long oi = (((long long)(b * NH + h)) * SSELF + s) * HDIM + dd;
        oq[oi] = __float2half_rn(rq * qscale);
        ok[oi] = __float2half_rn(rk);
    }
}

__global__ void __launch_bounds__(256) rms_heads_kernel(
    const f16* __restrict__ in, int ldin, int off,
    const float* __restrict__ w, f16* __restrict__ ob, int Srows,
    float outScale)
{
    long long r = blockIdx.x;
    int b = (int)(r / Srows), s = (int)(r % Srows);
    const f16* x = in + r * ldin + off;
    float s2 = 0.f;
    for (int d = threadIdx.x; d < D; d += 256) { float v = __half2float(x[d]); s2 += v * v; }
    s2 = blockReduceSum(s2);
    float rms = rsqrtf(s2 * (1.0f / D) + EPSV);
    for (int d = threadIdx.x; d < D; d += 256) {
        int h = d >> 7, dd = d & 127;
        float v = __half2float(x[d]) * rms * w[d];
        ob[(((long long)(b * NH + h)) * Srows + s) * HDIM + dd] = __float2half_rn(v * outScale);
    }
}

__global__ void vtrans_kernel(
    const f16* __restrict__ in, int ldin, int off,
    f16* __restrict__ out, int Srows)
{
    __shared__ f16 tile[32][33];
    int bz = blockIdx.z;
    int b = bz / NH, h = bz % NH;
    int s0 = blockIdx.x * 32, d0 = blockIdx.y * 32;
    int tx = threadIdx.x, ty = threadIdx.y;
    int colBase = off + h * HDIM + d0;
    #pragma unroll
    for (int i = 0; i < 4; i++) {
        int s = s0 + ty + i * 8;
        tile[ty + i * 8][tx] = in[(long long)(b * Srows + s) * ldin + colBase + tx];
    }
    __syncthreads();
    #pragma unroll
    for (int i = 0; i < 4; i++) {
        int d = d0 + ty + i * 8;
        out[((long long)bz * HDIM + d) * Srows + s0 + tx] = tile[tx][ty + i * 8];
    }
}

// 4-job segmented fp32->fp16 convert (each count in 8-element groups)
__global__ void __launch_bounds__(256) conv4_kernel(
    const float4* __restrict__ s0, uint4* __restrict__ d0, long long n0,
    const float4* __restrict__ s1, uint4* __restrict__ d1, long long n1,
    const float4* __restrict__ s2, uint4* __restrict__ d2, long long n2,
    const float4* __restrict__ s3, uint4* __restrict__ d3, long long n3)
{
    long long t0 = n0, t1 = t0 + n1, t2 = t1 + n2, t3 = t2 + n3;
    for (long long i = blockIdx.x * 256LL + threadIdx.x; i < t3; i += (long long)gridDim.x * 256) {
        const float4* s; uint4* d; long long off;
        if (i < t0)      { s = s0; d = d0; off = i; }
        else if (i < t1) { s = s1; d = d1; off = i - t0; }
        else if (i < t2) { s = s2; d = d2; off = i - t1; }
        else             { s = s3; d = d3; off = i - t2; }
        float4 a = s[2 * off], b = s[2 * off + 1];
        uint4 o;
        o.x = h2_bits(__floats2half2_rn(a.x, a.y));
        o.y = h2_bits(__floats2half2_rn(a.z, a.w));
        o.z = h2_bits(__floats2half2_rn(b.x, b.y));
        o.w = h2_bits(__floats2half2_rn(b.z, b.w));
        d[off] = o;
    }
}

// ---------------- flash attention ----------------
#define FA_NSTAGE 3
#define FA_QBYTES 32768
#define FA_SMEM   (FA_QBYTES + FA_NSTAGE * 32768)

__global__ void __launch_bounds__(256, 1) flash_kernel(
    const f16* __restrict__ Q, const f16* __restrict__ Kt, const f16* __restrict__ Vt,
    f16* __restrict__ Out, int Skv)
{
    extern __shared__ char smem[];
    uint32_t sbase = smem_u32(smem);
    int tid = threadIdx.x, wid = tid >> 5, lane = tid & 31;
    int q0 = blockIdx.x * 128;
    int bz = blockIdx.y;
    int b = bz / NH, hh = bz % NH;

    const f16* Qp = Q  + ((long long)bz * SSELF + q0) * HDIM;
    const f16* Kp = Kt + (long long)bz * Skv * HDIM;
    const f16* Vp = Vt + (long long)bz * HDIM * Skv;

    int NT = Skv >> 6;

    {
        int row = tid >> 1, cb = (tid & 1) * 8;
        #pragma unroll
        for (int i = 0; i < 8; i++)
            CP_ASYNC16(sbase + tswz2(row, cb + i), Qp + (long long)row * HDIM + (cb + i) * 8);
    }
    CP_COMMIT();

    auto load_kv = [&](int c) {
        int s = c % FA_NSTAGE;
        uint32_t stK = sbase + FA_QBYTES + s * 32768;
        uint32_t stV = stK + 16384;
        int k0 = c << 6;
        {
            int row = tid >> 2, cb = (tid & 3) * 4;
            #pragma unroll
            for (int i = 0; i < 4; i++)
                CP_ASYNC16(stK + tswz2(row, cb + i), Kp + (long long)(k0 + row) * HDIM + (cb + i) * 8);
        }
        {
            int row = tid >> 1, cb = (tid & 1) * 4;
            #pragma unroll
            for (int i = 0; i < 4; i++)
                CP_ASYNC16(stV + tswz(row, cb + i), Vp + (long long)row * Skv + k0 + (cb + i) * 8);
        }
    };

    load_kv(0); CP_COMMIT();
    if (NT > 1) load_kv(1);
    CP_COMMIT();

    CP_WAIT2();
    __syncthreads();
    uint32_t qf[8][4];
    {
        int rA = lane & 15, wq = wid * 16;
        #pragma unroll
        for (int ks = 0; ks < 8; ks++)
            ldsm4(qf[ks], sbase + tswz2(wq + rA, ks * 2 + (lane >> 4)));
    }

    float Oa[16][4];
    #pragma unroll
    for (int i = 0; i < 16; i++)
        #pragma unroll
        for (int e = 0; e < 4; e++) Oa[i][e] = 0.f;
    float m0 = -1e30f, m1 = -1e30f, l0 = 0.f, l1 = 0.f;

    int rB = (lane & 7) + ((lane >> 4) << 3);

    for (int c = 0; c < NT; c++) {
        int s = c % FA_NSTAGE;
        CP_WAIT1();
        __syncthreads();
        if (c + 2 < NT) load_kv(c + 2);
        CP_COMMIT();

        uint32_t stK = sbase + FA_QBYTES + s * 32768;
        uint32_t stV = stK + 16384;

        float Sa[8][4];
        #pragma unroll
        for (int i = 0; i < 8; i++)
            #pragma unroll
            for (int e = 0; e < 4; e++) Sa[i][e] = 0.f;
        #pragma unroll
        for (int ks = 0; ks < 8; ks++) {
            int cB = ks * 2 + ((lane >> 3) & 1);
            #pragma unroll
            for (int ntp = 0; ntp < 4; ntp++) {
                uint32_t t[4];
                ldsm4(t, stK + tswz2(ntp * 16 + rB, cB));
                mma16816h(Sa[2 * ntp],     qf[ks], t);
                mma16816h(Sa[2 * ntp + 1], qf[ks], t + 2);
            }
        }

        float tm0 = -1e30f, tm1 = -1e30f;
        #pragma unroll
        for (int nt = 0; nt < 8; nt++) {
            tm0 = fmaxf(tm0, fmaxf(Sa[nt][0], Sa[nt][1]));
            tm1 = fmaxf(tm1, fmaxf(Sa[nt][2], Sa[nt][3]));
        }
        tm0 = fmaxf(tm0, __shfl_xor_sync(0xffffffffu, tm0, 1));
        tm0 = fmaxf(tm0, __shfl_xor_sync(0xffffffffu, tm0, 2));
        tm1 = fmaxf(tm1, __shfl_xor_sync(0xffffffffu, tm1, 1));
        tm1 = fmaxf(tm1, __shfl_xor_sync(0xffffffffu, tm1, 2));
        float nm0 = fmaxf(m0, tm0), nm1 = fmaxf(m1, tm1);
        float cr0 = __expf(m0 - nm0), cr1 = __expf(m1 - nm1);
        m0 = nm0; m1 = nm1;
        float ls0 = 0.f, ls1 = 0.f;
        #pragma unroll
        for (int nt = 0; nt < 8; nt++) {
            Sa[nt][0] = __expf(Sa[nt][0] - m0);
            Sa[nt][1] = __expf(Sa[nt][1] - m0);
            Sa[nt][2] = __expf(Sa[nt][2] - m1);
            Sa[nt][3] = __expf(Sa[nt][3] - m1);
            ls0 += Sa[nt][0] + Sa[nt][1];
            ls1 += Sa[nt][2] + Sa[nt][3];
        }
        l0 = l0 * cr0 + ls0;
        l1 = l1 * cr1 + ls1;
        #pragma unroll
        for (int nt = 0; nt < 16; nt++) {
            Oa[nt][0] *= cr0; Oa[nt][1] *= cr0;
            Oa[nt][2] *= cr1; Oa[nt][3] *= cr1;
        }

        uint32_t pf[4][4];
        #pragma unroll
        for (int j = 0; j < 4; j++) {
            pf[j][0] = h2_bits(__floats2half2_rn(Sa[2 * j][0],     Sa[2 * j][1]));
            pf[j][1] = h2_bits(__floats2half2_rn(Sa[2 * j][2],     Sa[2 * j][3]));
            pf[j][2] = h2_bits(__floats2half2_rn(Sa[2 * j + 1][0], Sa[2 * j + 1][1]));
            pf[j][3] = h2_bits(__floats2half2_rn(Sa[2 * j + 1][2], Sa[2 * j + 1][3]));
        }
        #pragma unroll
        for (int j = 0; j < 4; j++) {
            int cV = j * 2 + ((lane >> 3) & 1);
            #pragma unroll
            for (int ntp = 0; ntp < 8; ntp++) {
                uint32_t t[4];
                ldsm4(t, stV + tswz(ntp * 16 + rB, cV));
                mma16816h(Oa[2 * ntp],     pf[j], t);
                mma16816h(Oa[2 * ntp + 1], pf[j], t + 2);
            }
        }
    }

    l0 += __shfl_xor_sync(0xffffffffu, l0, 1);
    l0 += __shfl_xor_sync(0xffffffffu, l0, 2);
    l1 += __shfl_xor_sync(0xffffffffu, l1, 1);
    l1 += __shfl_xor_sync(0xffffffffu, l1, 2);
    float inv0 = 1.0f / l0, inv1 = 1.0f / l1;
    int row0 = q0 + wid * 16 + (lane >> 2);
    int colB = hh * HDIM + (lane & 3) * 2;
    #pragma unroll
    for (int nt = 0; nt < 16; nt++) {
        int col = colB + nt * 8;
        long long i0 = ((long long)(b * SSELF + row0)) * D + col;
        long long i1 = ((long long)(b * SSELF + row0 + 8)) * D + col;
        Out[i0]     = __float2half_rn(Oa[nt][0] * inv0);
        Out[i0 + 1] = __float2half_rn(Oa[nt][1] * inv0);
        Out[i1]     = __float2half_rn(Oa[nt][2] * inv1);
        Out[i1 + 1] = __float2half_rn(Oa[nt][3] * inv1);
    }
}

// ---------------- fp16 GEMM: 2-stage, 3 CTAs/SM ----------------
#define STAGE_BYTES 32768
#define OFF_A 0
#define OFF_B 16384
#define GEMM_SMEM (2 * STAGE_BYTES)

__global__ void __launch_bounds__(128, 3) gemm_h1_kernel(
    const f16* __restrict__ A, const f16* __restrict__ B,
    float* __restrict__ C, f16* __restrict__ Cf,
    int K, int lda, int ldb, int ldc,
    const float* __restrict__ bias, float alpha, int mode,
    const float* __restrict__ res,
    const float* __restrict__ sst, const float* __restrict__ temb,
    int modIdx)
{
    extern __shared__ char smem[];
    uint32_t sbase = smem_u32(smem);
    int tid = threadIdx.x, wid = tid >> 5, lane = tid & 31;

    int m0 = blockIdx.y * 128, n0 = blockIdx.x * 128;
    const f16* Ap = A + (long long)m0 * lda;
    const f16* Bp = B + (long long)n0 * ldb;

    int lrow = tid >> 3, lch = tid & 7;
    int NC = K >> 6;

    auto load_stage = [&](int c) {
        int s = c & 1;
        uint32_t st = sbase + s * STAGE_BYTES;
        int k0 = c << 6;
        #pragma unroll
        for (int q = 0; q < 8; q++) {
            int row = lrow + q * 16;
            uint32_t sw = tswz(row, lch);
            long long gk = k0 + lch * 8;
            CP_ASYNC16(st + OFF_A + sw, Ap + (long long)row * lda + gk);
            CP_ASYNC16(st + OFF_B + sw, Bp + (long long)row * ldb + gk);
        }
    };

    float acc[4][8][4];
    #pragma unroll
    for (int i = 0; i < 4; i++)
        #pragma unroll
        for (int j = 0; j < 8; j++)
            #pragma unroll
            for (int e = 0; e < 4; e++) acc[i][j][e] = 0.f;

    int wm = (wid >> 1) * 64, wn = (wid & 1) * 64;

    load_stage(0); CP_COMMIT();
    if (NC > 1) load_stage(1);
    CP_COMMIT();

    for (int c = 0; c < NC; c++) {
        uint32_t st = sbase + (c & 1) * STAGE_BYTES;
        CP_WAIT1();
        __syncthreads();
        #pragma unroll
        for (int kk = 0; kk < 4; kk++) {
            uint32_t af[4][4];
            int rA = lane & 15, cA = (kk << 1) + (lane >> 4);
            #pragma unroll
            for (int mt = 0; mt < 4; mt++)
                ldsm4(af[mt], st + OFF_A + tswz(wm + mt * 16 + rA, cA));
            int rB = (lane & 7) + ((lane >> 4) << 3);
            int cB = (kk << 1) + ((lane >> 3) & 1);
            #pragma unroll
            for (int ntp = 0; ntp < 4; ntp++) {
                uint32_t t[4];
                ldsm4(t, st + OFF_B + tswz(wn + ntp * 16 + rB, cB));
                #pragma unroll
                for (int mt = 0; mt < 4; mt++) {
                    mma16816h(acc[mt][2 * ntp],     af[mt], t);
                    mma16816h(acc[mt][2 * ntp + 1], af[mt], t + 2);
                }
            }
        }
        __syncthreads();
        if (c + 2 < NC) { load_stage(c + 2); CP_COMMIT(); }
    }

    int qrow = lane >> 2, qcol = (lane & 3) * 2;
    #pragma unroll
    for (int mt = 0; mt < 4; mt++) {
        #pragma unroll
        for (int nt = 0; nt < 8; nt++) {
            #pragma unroll
            for (int e = 0; e < 4; e++) {
                long long rrow = m0 + wm + mt * 16 + qrow + ((e >> 1) ? 8 : 0);
                int col = n0 + wn + nt * 8 + qcol + (e & 1);
                float v = acc[mt][nt][e] * alpha;
                if (bias) v += bias[col];
                if (mode == 1) v = fast_gelu(v);
                long long ci = rrow * (long long)ldc + col;
                if (mode == 2) {
                    int b_ = (int)(rrow >> 11);
                    float g = sst[(long long)modIdx * D + col] +
                              temb[((long long)b_ * 6 + modIdx) * D + col];
                    v = res[ci] + g * v;
                } else if (mode == 3) {
                    v = res[ci] + v;
                }
                if (C)  C[ci]  = v;
                if (Cf) Cf[ci] = __float2half_rn(v);
            }
        }
    }
}

// ---------------- host launch helper ----------------
static void gemm(const f16* A, const f16* B, float* C, f16* Cf,
                 int M, int N, int K, int lda, int ldb, int ldc,
                 const float* bias, float alpha, int mode,
                 const float* res, const float* sst, const float* temb,
                 int modIdx)
{
    dim3 grid(N / 128, M / 128, 1), block(128);
    gemm_h1_kernel<<<grid, block, GEMM_SMEM>>>(
        A, B, C, Cf, K, lda, ldb, ldc,
        bias, alpha, mode, res, sst, temb, modIdx);
}

#define GETP(sym) ({ void* _p; cudaGetSymbolAddress(&_p, sym); _p; })

extern "C" void kernel_launch(void* const* d_in, const int* in_sizes, int n_in,
                              void* d_out, int out_size)
{
    const float* h    = (const float*)d_in[0];
    const float* enc  = (const float*)d_in[1];
    const float* temb = (const float*)d_in[2];
    const float* rcos = (const float*)d_in[3];
    const float* rsin = (const float*)d_in[4];
    const float* sst  = (const float*)d_in[5];
    const float* w_qkv = (const float*)d_in[6];
    const float* b_qkv = (const float*)d_in[7];
    const float* rms_q1 = (const float*)d_in[8];
    const float* rms_k1 = (const float*)d_in[9];
    const float* w_o1 = (const float*)d_in[10];
    const float* b_o1 = (const float*)d_in[11];
    const float* ln2_g = (const float*)d_in[12];
    const float* ln2_b = (const float*)d_in[13];
    const float* w_q2 = (const float*)d_in[14];
    const float* b_q2 = (const float*)d_in[15];
    const float* w_kv2 = (const float*)d_in[16];
    const float* b_kv2 = (const float*)d_in[17];
    const float* rms_q2 = (const float*)d_in[18];
    const float* rms_k2 = (const float*)d_in[19];
    const float* w_o2 = (const float*)d_in[20];
    const float* b_o2 = (const float*)d_in[21];
    const float* w_ff1 = (const float*)d_in[22];
    const float* b_ff1 = (const float*)d_in[23];
    const float* w_ff2 = (const float*)d_in[24];
    const float* b_ff2 = (const float*)d_in[25];
    float* out = (float*)d_out;

    cudaFuncSetAttribute(gemm_h1_kernel, cudaFuncAttributeMaxDynamicSharedMemorySize, GEMM_SMEM);
    cudaFuncSetAttribute(flash_kernel,  cudaFuncAttributeMaxDynamicSharedMemorySize, FA_SMEM);

    float* ph1  = (float*)GETP(g_h1);
    float* ph2  = (float*)GETP(g_h2);
    f16 *qkvh=(f16*)GETP(g_qkvh);
    f16 *kv2h=(f16*)GETP(g_kv2h);
    f16 *xb=(f16*)GETP(g_x);
    f16 *qb=(f16*)GETP(g_q);
    f16 *ab=(f16*)GETP(g_a);
    f16 *mb=(f16*)GETP(g_m);
    f16 *encb=(f16*)GETP(g_enc);
    f16 *kb=(f16*)GETP(g_kb), *vb=(f16*)GETP(g_vb);
    f16 *wqkv=(f16*)GETP(g_wqkv);
    f16 *wo1=(f16*)GETP(g_wo1);
    f16 *wq2=(f16*)GETP(g_wq2);
    f16 *wkv2=(f16*)GETP(g_wkv2);
    f16 *wo2=(f16*)GETP(g_wo2);
    f16 *wff1=(f16*)GETP(g_wff1);
    f16 *wff2=(f16*)GETP(g_wff2);

    const float scale = 0.08838834764831845f;
    const long long DD8 = (long long)D * D / 8;

    // 0) conv A: wqkv, wff1, wff2, wo1
    conv4_kernel<<<2048, 256>>>(
        (const float4*)w_qkv, (uint4*)wqkv, 3 * DD8,
        (const float4*)w_ff1, (uint4*)wff1, 4 * DD8,
        (const float4*)w_ff2, (uint4*)wff2, 4 * DD8,
        (const float4*)w_o1,  (uint4*)wo1,  DD8);
    // 1) conv B: wq2, wkv2, wo2, enc
    conv4_kernel<<<1024, 256>>>(
        (const float4*)w_q2,  (uint4*)wq2,  DD8,
        (const float4*)w_kv2, (uint4*)wkv2, 2 * DD8,
        (const float4*)w_o2,  (uint4*)wo2,  DD8,
        (const float4*)enc,   (uint4*)encb, (long long)TOKC * D / 8);
    // 2) ln
    ln_kernel<<<TOK, 256>>>(h, xb, nullptr, nullptr, sst, temb, 0, 1, SSELF);
    // 3) qkv GEMM (profiled)
    gemm(xb, wqkv, nullptr, qkvh, TOK, 3 * D, D, D, D, 3 * D,
         b_qkv, 1.f, 0, nullptr, nullptr, nullptr, 0);
    // fused q+k heads
    rmsqk_kernel<<<TOK, 256>>>(qkvh, rms_q1, rms_k1, qb, kb, rcos, rsin, scale);
    {
        dim3 tb(32, 8), tg(SSELF / 32, HDIM / 32, BH);
        vtrans_kernel<<<tg, tb>>>(qkvh, 3 * D, 2 * D, vb, SSELF);
    }
    // flash self-attention
    flash_kernel<<<dim3(SSELF / 128, BH), 256, FA_SMEM>>>(qb, kb, vb, ab, SSELF);
    // h1 = h + gate_sa * (attn W_o1^T + b)
    gemm(ab, wo1, ph1, nullptr, TOK, D, D, D, D, D,
         b_o1, 1.f, 2, h, sst, temb, 2);
    // x2 = LN(h1)
    ln_kernel<<<TOK, 256>>>(ph1, xb, ln2_g, ln2_b, nullptr, nullptr, 0, 0, SSELF);
    // q2lin
    gemm(xb, wq2, nullptr, qkvh, TOK, D, D, D, D, D,
         b_q2, 1.f, 0, nullptr, nullptr, nullptr, 0);
    rms_heads_kernel<<<TOK, 256>>>(qkvh, D, 0, rms_q2, qb, SSELF, scale);
    // kv2
    gemm(encb, wkv2, nullptr, kv2h, TOKC, 2 * D, D, D, D, 2 * D,
         b_kv2, 1.f, 0, nullptr, nullptr, nullptr, 0);
    rms_heads_kernel<<<TOKC, 256>>>(kv2h, 2 * D, 0, rms_k2, kb, SCROSS, 1.f);
    {
        dim3 tb(32, 8), tg(SCROSS / 32, HDIM / 32, BH);
        vtrans_kernel<<<tg, tb>>>(kv2h, 2 * D, D, vb, SCROSS);
    }
    // flash cross-attention
    flash_kernel<<<dim3(SSELF / 128, BH), 256, FA_SMEM>>>(qb, kb, vb, ab, SCROSS);
    // h2 = h1 + attn2 W_o2^T + b
    gemm(ab, wo2, ph2, nullptr, TOK, D, D, D, D, D,
         b_o2, 1.f, 3, ph1, nullptr, nullptr, 0);
    // xff
    ln_kernel<<<TOK, 256>>>(ph2, xb, nullptr, nullptr, sst, temb, 3, 4, SSELF);
    // mid = gelu(xff W_ff1^T + b)
    gemm(xb, wff1, nullptr, mb, TOK, FFND, D, D, D, FFND,
         b_ff1, 1.f, 1, nullptr, nullptr, nullptr, 0);
    // out = h2 + gate_ff * (mid W_ff2^T + b)
    gemm(mb, wff2, out, nullptr, TOK, D, FFND, FFND, FFND, D,
         b_ff2, 1.f, 2, ph2, sst, temb, 5);

    (void)in_sizes; (void)n_in; (void)out_size;
}